// round 1
// baseline (speedup 1.0000x reference)
#include <cuda_runtime.h>
#include <math.h>
#include <math_constants.h>

#define BB 2
#define SS 2048
#define NH 16
#define DH 64
#define HID 1024
#define HALF 256
#define SCALE 0.125f   /* 64^-0.5 */

#define OUT_ELEMS  (BB*SS*HID)                 /* 4194304 */
#define ATTN_ELEMS ((size_t)BB*NH*SS*SS)       /* 134217728 */

/* scratch (no cudaMalloc allowed) */
__device__ float g_q[BB*NH*SS*DH];
__device__ float g_k[BB*NH*SS*DH];
__device__ float g_v[BB*NH*SS*DH];
__device__ float g_ctx[BB*SS*HID];

/* ---------------- GEMM: Y = X @ W^T ----------------
 * X: [M,1024] row-major, W: [1024,1024] row-major (o,h)
 * MODE 0: scatter Y[m, o] -> [B,H,S,D] qkv layout
 * MODE 1: plain Y[m, o] row-major
 * Tile 128x128x16, 256 threads, 8x8 microtile.
 */
template<int MODE>
__global__ __launch_bounds__(256, 2)
void gemm_kernel(const float* __restrict__ X, const float* __restrict__ W,
                 float* __restrict__ Y, int M)
{
    const int BM = 128, BN = 128, BK = 16;
    __shared__ float As[BK][BM + 1];
    __shared__ float Bs[BK][BN + 1];

    int tid = threadIdx.x;
    int bm = blockIdx.y * BM;
    int bn = blockIdx.x * BN;
    int tx = tid & 15;        /* 0..15 */
    int ty = tid >> 4;        /* 0..15 */

    float acc[8][8];
#pragma unroll
    for (int i = 0; i < 8; i++)
#pragma unroll
        for (int j = 0; j < 8; j++) acc[i][j] = 0.f;

    for (int k0 = 0; k0 < 1024; k0 += BK) {
#pragma unroll
        for (int l = 0; l < 8; l++) {
            int idx = tid + l * 256;          /* 0..2047 */
            int m   = idx >> 4;               /* row in tile */
            int kk  = idx & 15;
            As[kk][m] = X[(size_t)(bm + m) * 1024 + k0 + kk];
        }
#pragma unroll
        for (int l = 0; l < 8; l++) {
            int idx = tid + l * 256;
            int n   = idx >> 4;
            int kk  = idx & 15;
            Bs[kk][n] = W[(size_t)(bn + n) * 1024 + k0 + kk];
        }
        __syncthreads();
#pragma unroll
        for (int kk = 0; kk < BK; kk++) {
            float ra[8], rb[8];
#pragma unroll
            for (int i = 0; i < 8; i++) ra[i] = As[kk][ty * 8 + i];
#pragma unroll
            for (int j = 0; j < 8; j++) rb[j] = Bs[kk][tx * 8 + j];
#pragma unroll
            for (int i = 0; i < 8; i++)
#pragma unroll
                for (int j = 0; j < 8; j++)
                    acc[i][j] += ra[i] * rb[j];
        }
        __syncthreads();
    }

#pragma unroll
    for (int i = 0; i < 8; i++) {
        int m = bm + ty * 8 + i;
        int b = m / SS, s = m % SS;
#pragma unroll
        for (int j = 0; j < 8; j++) {
            int n = bn + tx * 8 + j;
            if (MODE == 0) {
                int h = n >> 6, d = n & 63;
                Y[(((size_t)b * NH + h) * SS + s) * DH + d] = acc[i][j];
            } else {
                Y[(size_t)m * HID + n] = acc[i][j];
            }
        }
    }
}

/* ---------------- Sliding-window attention ----------------
 * Block: TR=32 query rows of one (b,h). 256 threads.
 * Window union width = TR-1 + 2*HALF + 1 = 544 -> 17 chunks of 32.
 * Shared: sQ[32][64], sKV[32][65], sS[32][544]  (~86 KB dynamic)
 */
#define TR   32
#define WW   544
#define NCH  17
#define NEGINF (-1e30f)

extern __shared__ float smem_attn[];

__global__ __launch_bounds__(256, 2)
void attn_kernel(float* __restrict__ attn_out, int write_attn)
{
    int bh = blockIdx.y;            /* 0..31 */
    int i0 = blockIdx.x * TR;
    int b = bh / NH, h = bh % NH;
    const float* Q = g_q + (size_t)bh * SS * DH;
    const float* K = g_k + (size_t)bh * SS * DH;
    const float* V = g_v + (size_t)bh * SS * DH;

    float* sQ  = smem_attn;                 /* [TR][DH]    2048 */
    float* sKV = sQ + TR * DH;              /* [32][65]    2080 */
    float* sS  = sKV + 32 * 65;             /* [TR][WW]   17408 */

    int tid = threadIdx.x;

    /* load Q tile (pre-scaled) */
    for (int idx = tid; idx < TR * DH; idx += 256) {
        int r = idx >> 6, d = idx & 63;
        sQ[r * DH + d] = Q[(size_t)(i0 + r) * DH + d] * SCALE;
    }

    int jlo = i0 - HALF;   /* may be negative */

    /* ---- scores ---- */
    int tx = tid & 31, tg = tid >> 5;   /* tg: 0..7 */
    for (int c = 0; c < NCH; c++) {
        int jbase = jlo + c * 32;
        __syncthreads();
        for (int idx = tid; idx < 32 * DH; idx += 256) {
            int jj = idx >> 6, d = idx & 63;
            int j = jbase + jj;
            sKV[jj * 65 + d] = (j >= 0 && j < SS) ? K[(size_t)j * DH + d] : 0.f;
        }
        __syncthreads();
#pragma unroll
        for (int rr = 0; rr < 4; rr++) {
            int r = tg + rr * 8;
            int i = i0 + r;
            int j = jbase + tx;
            float sum = 0.f;
#pragma unroll
            for (int d = 0; d < DH; d++)
                sum += sQ[r * DH + d] * sKV[tx * 65 + d];
            bool valid = (j >= 0) && (j < SS) && (j >= i - HALF) && (j <= i + HALF);
            sS[r * WW + c * 32 + tx] = valid ? sum : NEGINF;
        }
    }
    __syncthreads();

    /* ---- softmax (warp per 4 rows) ---- */
    int warp = tid >> 5, lane = tid & 31;
#pragma unroll
    for (int rr = 0; rr < 4; rr++) {
        int r = warp + rr * 8;
        float mx = NEGINF;
        for (int cc = lane; cc < WW; cc += 32) mx = fmaxf(mx, sS[r * WW + cc]);
#pragma unroll
        for (int o = 16; o > 0; o >>= 1) mx = fmaxf(mx, __shfl_xor_sync(0xffffffffu, mx, o));
        float sm = 0.f;
        for (int cc = lane; cc < WW; cc += 32) {
            float s = sS[r * WW + cc];
            float e = (s <= NEGINF) ? 0.f : __expf(s - mx);
            sS[r * WW + cc] = e;
            sm += e;
        }
#pragma unroll
        for (int o = 16; o > 0; o >>= 1) sm += __shfl_xor_sync(0xffffffffu, sm, o);
        float inv = 1.f / sm;
        for (int cc = lane; cc < WW; cc += 32) sS[r * WW + cc] *= inv;
    }
    __syncthreads();

    /* ---- write full attn rows (zeros outside window) ---- */
    if (write_attn) {
#pragma unroll
        for (int rr = 0; rr < 4; rr++) {
            int r = warp + rr * 8;
            int i = i0 + r;
            float* row = attn_out + ((size_t)bh * SS + i) * SS;
            for (int j = lane; j < SS; j += 32) {
                int cidx = j - jlo;
                float p = (cidx >= 0 && cidx < WW) ? sS[r * WW + cidx] : 0.f;
                row[j] = p;
            }
        }
    }

    /* ---- PV: O[r][d] accumulation ---- */
    int d  = tid & 63;
    int rg = tid >> 6;   /* 0..3 : rows rg, rg+4, ..., rg+28 */
    float acc[8];
#pragma unroll
    for (int rr = 0; rr < 8; rr++) acc[rr] = 0.f;

    for (int c = 0; c < NCH; c++) {
        int jbase = jlo + c * 32;
        __syncthreads();
        for (int idx = tid; idx < 32 * DH; idx += 256) {
            int jj = idx >> 6, dd = idx & 63;
            int j = jbase + jj;
            sKV[jj * 65 + dd] = (j >= 0 && j < SS) ? V[(size_t)j * DH + dd] : 0.f;
        }
        __syncthreads();
#pragma unroll
        for (int jj = 0; jj < 32; jj++) {
            float vv = sKV[jj * 65 + d];
#pragma unroll
            for (int rr = 0; rr < 8; rr++)
                acc[rr] += sS[(rg + rr * 4) * WW + c * 32 + jj] * vv;
        }
    }

#pragma unroll
    for (int rr = 0; rr < 8; rr++) {
        int i = i0 + rg + rr * 4;
        g_ctx[((size_t)b * SS + i) * HID + h * DH + d] = acc[rr];
    }
}

extern "C" void kernel_launch(void* const* d_in, const int* in_sizes, int n_in,
                              void* d_out, int out_size)
{
    const float* X  = (const float*)d_in[0];
    const float* Wq = (const float*)d_in[1];
    const float* Wk = (const float*)d_in[2];
    const float* Wv = (const float*)d_in[3];
    const float* Wo = (const float*)d_in[4];
    float* out = (float*)d_out;

    float *q, *k, *v, *ctx;
    cudaGetSymbolAddress((void**)&q,   g_q);
    cudaGetSymbolAddress((void**)&k,   g_k);
    cudaGetSymbolAddress((void**)&v,   g_v);
    cudaGetSymbolAddress((void**)&ctx, g_ctx);

    int M = BB * SS;                 /* 4096 */
    dim3 ggrid(HID / 128, M / 128);  /* (8, 32) */

    gemm_kernel<0><<<ggrid, 256>>>(X, Wq, q, M);
    gemm_kernel<0><<<ggrid, 256>>>(X, Wk, k, M);
    gemm_kernel<0><<<ggrid, 256>>>(X, Wv, v, M);

    int write_attn = ((size_t)out_size >= (size_t)OUT_ELEMS + ATTN_ELEMS) ? 1 : 0;
    float* attn_out = write_attn ? (out + OUT_ELEMS) : out;

    size_t smem_bytes = (size_t)(TR * DH + 32 * 65 + TR * WW) * sizeof(float); /* ~86 KB */
    static int attr_set = -1;
    if (attr_set < 0) {
        cudaFuncSetAttribute(attn_kernel, cudaFuncAttributeMaxDynamicSharedMemorySize,
                             (int)smem_bytes);
        attr_set = 1;
    }
    dim3 agrid(SS / TR, BB * NH);    /* (64, 32) */
    attn_kernel<<<agrid, 256, smem_bytes>>>(attn_out, write_attn);

    gemm_kernel<1><<<ggrid, 256>>>(ctx, Wo, out, M);
}

// round 4
// speedup vs baseline: 2.2076x; 2.2076x over previous
#include <cuda_runtime.h>
#include <cuda_bf16.h>
#include <cstdint>
#include <math.h>

#define BB 2
#define SS 2048
#define NH 16
#define DH 64
#define HID 1024
#define HALF 256
#define SCALE 0.125f
#define MTOT 4096

#define OUT_ELEMS  (BB*SS*HID)
#define ATTN_ELEMS ((size_t)BB*NH*SS*SS)

/* ---------------- scratch (no cudaMalloc allowed) ---------------- */
__device__ float g_q[BB*NH*SS*DH];
__device__ float g_k[BB*NH*SS*DH];
__device__ float g_v[BB*NH*SS*DH];
__device__ float g_ctx[BB*SS*HID];
__device__ __nv_bfloat16 g_xh[MTOT*HID];
__device__ __nv_bfloat16 g_xl[MTOT*HID];
__device__ __nv_bfloat16 g_wh[4][HID*HID];
__device__ __nv_bfloat16 g_wl[4][HID*HID];

/* ---------------- helpers ---------------- */
__device__ __forceinline__ uint32_t smem_u32(const void* p) {
    uint32_t a;
    asm("{ .reg .u64 t; cvta.to.shared.u64 t, %1; cvt.u32.u64 %0, t; }" : "=r"(a) : "l"(p));
    return a;
}
#define CP_ASYNC16(dst, src) asm volatile("cp.async.cg.shared.global [%0], [%1], 16;" :: "r"(dst), "l"(src))
#define CP_COMMIT()          asm volatile("cp.async.commit_group;" ::: "memory")
#define CP_WAIT1()           asm volatile("cp.async.wait_group 1;" ::: "memory")
#define CP_WAIT0()           asm volatile("cp.async.wait_group 0;" ::: "memory")

#define LDMX4(r0,r1,r2,r3,addr) \
    asm volatile("ldmatrix.sync.aligned.m8n8.x4.shared.b16 {%0,%1,%2,%3}, [%4];" \
        : "=r"(r0), "=r"(r1), "=r"(r2), "=r"(r3) : "r"(addr))
#define LDMX2(r0,r1,addr) \
    asm volatile("ldmatrix.sync.aligned.m8n8.x2.shared.b16 {%0,%1}, [%2];" \
        : "=r"(r0), "=r"(r1) : "r"(addr))

#define MMA16816(c, a, b) \
    asm volatile("mma.sync.aligned.m16n8k16.row.col.f32.bf16.bf16.f32 " \
        "{%0,%1,%2,%3}, {%4,%5,%6,%7}, {%8,%9}, {%0,%1,%2,%3};" \
        : "+f"((c)[0]), "+f"((c)[1]), "+f"((c)[2]), "+f"((c)[3]) \
        : "r"((a)[0]), "r"((a)[1]), "r"((a)[2]), "r"((a)[3]), "r"((b)[0]), "r"((b)[1]))

/* ---------------- fp32 -> bf16 hi/lo split ---------------- */
__global__ void split_kernel(const float4* __restrict__ src,
                             __nv_bfloat162* __restrict__ hi,
                             __nv_bfloat162* __restrict__ lo, int n4)
{
    for (int i = blockIdx.x * blockDim.x + threadIdx.x; i < n4; i += gridDim.x * blockDim.x) {
        float4 x = src[i];
        __nv_bfloat16 h0 = __float2bfloat16(x.x), h1 = __float2bfloat16(x.y);
        __nv_bfloat16 h2 = __float2bfloat16(x.z), h3 = __float2bfloat16(x.w);
        float r0 = x.x - __bfloat162float(h0), r1 = x.y - __bfloat162float(h1);
        float r2 = x.z - __bfloat162float(h2), r3 = x.w - __bfloat162float(h3);
        hi[2*i]   = __nv_bfloat162(h0, h1);
        hi[2*i+1] = __nv_bfloat162(h2, h3);
        lo[2*i]   = __nv_bfloat162(__float2bfloat16(r0), __float2bfloat16(r1));
        lo[2*i+1] = __nv_bfloat162(__float2bfloat16(r2), __float2bfloat16(r3));
    }
}

/* ---------------- mma.sync split GEMM: Y = (Ah+Al)@(Bh+Bl)^T ----------------
 * A: [4096,1024] bf16 K-major; W: [1024,1024] bf16 K-major.
 * CTA tile 128x128, BK=32, 8 warps (2x4), warp tile 64x32.
 * Smem per stage: 4 tiles [128][40] bf16 (pad 8 -> 80B rows), 40960 B; x2 stages.
 * 3 passes: AhBh + AlBh + AhBl, accumulated in f32.
 */
extern __shared__ char dyn_smem[];

#define TPAD 40              /* bf16 per padded row */
#define TROWB 80             /* bytes per padded row */
#define TILEB (128*TROWB)    /* 10240 bytes per tile */
#define STAGEB (4*TILEB)     /* 40960 */

template<int MODE>
__global__ __launch_bounds__(256, 2)
void mma_gemm(const __nv_bfloat16* __restrict__ Ah, const __nv_bfloat16* __restrict__ Al,
              const __nv_bfloat16* __restrict__ Bh, const __nv_bfloat16* __restrict__ Bl,
              float* __restrict__ Y)
{
    uint32_t sb = smem_u32(dyn_smem);
    int tid = threadIdx.x, warp = tid >> 5, lane = tid & 31;
    int warpM = warp >> 2, warpN = warp & 3;          /* 2 x 4 */
    int bm = blockIdx.y * 128, bn = blockIdx.x * 128;

    float acc[4][4][4];
#pragma unroll
    for (int i = 0; i < 4; i++)
#pragma unroll
        for (int j = 0; j < 4; j++)
#pragma unroll
            for (int t = 0; t < 4; t++) acc[i][j][t] = 0.f;

    const __nv_bfloat16* srcs[4] = {Ah, Al, Bh, Bl};

    /* per-thread copy decomposition: idx = tid + v*256, v=0..7
       t = idx>>9, r = (idx>>2)&127, seg = idx&3 */
    auto issue_stage = [&](int s, int k0) {
        uint32_t base = sb + s * STAGEB;
#pragma unroll
        for (int v = 0; v < 8; v++) {
            int idx = tid + v * 256;
            int t = idx >> 9, r = (idx >> 2) & 127, seg = idx & 3;
            int rbase = (t < 2) ? bm : bn;
            const __nv_bfloat16* src = srcs[t] + (size_t)(rbase + r) * 1024 + k0 + seg * 8;
            uint32_t dst = base + t * TILEB + r * TROWB + seg * 16;
            CP_ASYNC16(dst, src);
        }
        CP_COMMIT();
    };

    /* ldmatrix address components (bytes within a tile) */
    uint32_t aRowOff = (uint32_t)((warpM * 64 + (lane & 7) + ((lane >> 3) & 1) * 8) * TROWB
                                  + ((lane >> 4) * 8) * 2);
    uint32_t bRowOff = (uint32_t)((warpN * 32 + (lane & 7)) * TROWB
                                  + (((lane >> 3) & 1) * 8) * 2);

    issue_stage(0, 0);

    for (int it = 0; it < 32; it++) {
        if (it + 1 < 32) issue_stage((it + 1) & 1, (it + 1) * 32);
        if (it + 1 < 32) CP_WAIT1(); else CP_WAIT0();
        __syncthreads();

        uint32_t st = sb + (it & 1) * STAGEB;
        uint32_t ah_b = st + aRowOff;
        uint32_t al_b = st + TILEB + aRowOff;
        uint32_t bh_b = st + 2 * TILEB + bRowOff;
        uint32_t bl_b = st + 3 * TILEB + bRowOff;

#pragma unroll
        for (int ks = 0; ks < 2; ks++) {
            uint32_t ko = ks * 32;   /* 16 bf16 = 32 bytes */
            uint32_t aH[4][4], aL[4][4], bb[4][2];
#pragma unroll
            for (int mt = 0; mt < 4; mt++)
                LDMX4(aH[mt][0], aH[mt][1], aH[mt][2], aH[mt][3], ah_b + mt * (16 * TROWB) + ko);
#pragma unroll
            for (int nt = 0; nt < 4; nt++)
                LDMX2(bb[nt][0], bb[nt][1], bh_b + nt * (8 * TROWB) + ko);
#pragma unroll
            for (int mt = 0; mt < 4; mt++)
#pragma unroll
                for (int nt = 0; nt < 4; nt++)
                    MMA16816(acc[mt][nt], aH[mt], bb[nt]);
#pragma unroll
            for (int mt = 0; mt < 4; mt++)
                LDMX4(aL[mt][0], aL[mt][1], aL[mt][2], aL[mt][3], al_b + mt * (16 * TROWB) + ko);
#pragma unroll
            for (int mt = 0; mt < 4; mt++)
#pragma unroll
                for (int nt = 0; nt < 4; nt++)
                    MMA16816(acc[mt][nt], aL[mt], bb[nt]);
#pragma unroll
            for (int nt = 0; nt < 4; nt++)
                LDMX2(bb[nt][0], bb[nt][1], bl_b + nt * (8 * TROWB) + ko);
#pragma unroll
            for (int mt = 0; mt < 4; mt++)
#pragma unroll
                for (int nt = 0; nt < 4; nt++)
                    MMA16816(acc[mt][nt], aH[mt], bb[nt]);
        }
        __syncthreads();
    }

    /* epilogue */
    int row0 = lane >> 2, col0 = (lane & 3) * 2;
#pragma unroll
    for (int mt = 0; mt < 4; mt++) {
#pragma unroll
        for (int half = 0; half < 2; half++) {
            int m = bm + warpM * 64 + mt * 16 + row0 + half * 8;
            int b = m >> 11, s = m & 2047;
#pragma unroll
            for (int nt = 0; nt < 4; nt++) {
                int n = bn + warpN * 32 + nt * 8 + col0;
                float2 v2;
                v2.x = acc[mt][nt][half * 2 + 0];
                v2.y = acc[mt][nt][half * 2 + 1];
                if (MODE == 0) {
                    int h = n >> 6, d0 = n & 63;
                    *(float2*)(Y + (((size_t)b * NH + h) * SS + s) * DH + d0) = v2;
                } else {
                    *(float2*)(Y + (size_t)m * HID + n) = v2;
                }
            }
        }
    }
}

/* ---------------- Sliding-window attention (unchanged from R1) ---------------- */
#define TR   32
#define WW   544
#define NCH  17
#define NEGINF (-1e30f)

__global__ __launch_bounds__(256, 2)
void attn_kernel(float* __restrict__ attn_out, int write_attn)
{
    int bh = blockIdx.y;
    int i0 = blockIdx.x * TR;
    int b = bh / NH, h = bh % NH;
    const float* Q = g_q + (size_t)bh * SS * DH;
    const float* K = g_k + (size_t)bh * SS * DH;
    const float* V = g_v + (size_t)bh * SS * DH;

    float* sQ  = (float*)dyn_smem;
    float* sKV = sQ + TR * DH;
    float* sS  = sKV + 32 * 65;

    int tid = threadIdx.x;
    for (int idx = tid; idx < TR * DH; idx += 256) {
        int r = idx >> 6, d = idx & 63;
        sQ[r * DH + d] = Q[(size_t)(i0 + r) * DH + d] * SCALE;
    }
    int jlo = i0 - HALF;

    int tx = tid & 31, tg = tid >> 5;
    for (int c = 0; c < NCH; c++) {
        int jbase = jlo + c * 32;
        __syncthreads();
        for (int idx = tid; idx < 32 * DH; idx += 256) {
            int jj = idx >> 6, d = idx & 63;
            int j = jbase + jj;
            sKV[jj * 65 + d] = (j >= 0 && j < SS) ? K[(size_t)j * DH + d] : 0.f;
        }
        __syncthreads();
#pragma unroll
        for (int rr = 0; rr < 4; rr++) {
            int r = tg + rr * 8;
            int i = i0 + r;
            int j = jbase + tx;
            float sum = 0.f;
#pragma unroll
            for (int d = 0; d < DH; d++)
                sum += sQ[r * DH + d] * sKV[tx * 65 + d];
            bool valid = (j >= 0) && (j < SS) && (j >= i - HALF) && (j <= i + HALF);
            sS[r * WW + c * 32 + tx] = valid ? sum : NEGINF;
        }
    }
    __syncthreads();

    int warp = tid >> 5, lane = tid & 31;
#pragma unroll
    for (int rr = 0; rr < 4; rr++) {
        int r = warp + rr * 8;
        float mx = NEGINF;
        for (int cc = lane; cc < WW; cc += 32) mx = fmaxf(mx, sS[r * WW + cc]);
#pragma unroll
        for (int o = 16; o > 0; o >>= 1) mx = fmaxf(mx, __shfl_xor_sync(0xffffffffu, mx, o));
        float sm = 0.f;
        for (int cc = lane; cc < WW; cc += 32) {
            float s = sS[r * WW + cc];
            float e = (s <= NEGINF) ? 0.f : __expf(s - mx);
            sS[r * WW + cc] = e;
            sm += e;
        }
#pragma unroll
        for (int o = 16; o > 0; o >>= 1) sm += __shfl_xor_sync(0xffffffffu, sm, o);
        float inv = 1.f / sm;
        for (int cc = lane; cc < WW; cc += 32) sS[r * WW + cc] *= inv;
    }
    __syncthreads();

    if (write_attn) {
#pragma unroll
        for (int rr = 0; rr < 4; rr++) {
            int r = warp + rr * 8;
            int i = i0 + r;
            float* row = attn_out + ((size_t)bh * SS + i) * SS;
            for (int j = lane; j < SS; j += 32) {
                int cidx = j - jlo;
                float p = (cidx >= 0 && cidx < WW) ? sS[r * WW + cidx] : 0.f;
                row[j] = p;
            }
        }
    }

    int d  = tid & 63;
    int rg = tid >> 6;
    float acc[8];
#pragma unroll
    for (int rr = 0; rr < 8; rr++) acc[rr] = 0.f;

    for (int c = 0; c < NCH; c++) {
        int jbase = jlo + c * 32;
        __syncthreads();
        for (int idx = tid; idx < 32 * DH; idx += 256) {
            int jj = idx >> 6, dd = idx & 63;
            int j = jbase + jj;
            sKV[jj * 65 + dd] = (j >= 0 && j < SS) ? V[(size_t)j * DH + dd] : 0.f;
        }
        __syncthreads();
#pragma unroll
        for (int jj = 0; jj < 32; jj++) {
            float vv = sKV[jj * 65 + d];
#pragma unroll
            for (int rr = 0; rr < 8; rr++)
                acc[rr] += sS[(rg + rr * 4) * WW + c * 32 + jj] * vv;
        }
    }
#pragma unroll
    for (int rr = 0; rr < 8; rr++) {
        int i = i0 + rg + rr * 4;
        g_ctx[((size_t)b * SS + i) * HID + h * DH + d] = acc[rr];
    }
}

/* ---------------- launch ---------------- */
extern "C" void kernel_launch(void* const* d_in, const int* in_sizes, int n_in,
                              void* d_out, int out_size)
{
    const float* X = (const float*)d_in[0];
    const float* W[4] = {(const float*)d_in[1], (const float*)d_in[2],
                         (const float*)d_in[3], (const float*)d_in[4]};
    float* out = (float*)d_out;

    float *q, *k, *v, *ctx;
    __nv_bfloat16 *xh, *xl, *wh, *wl;
    cudaGetSymbolAddress((void**)&q, g_q);
    cudaGetSymbolAddress((void**)&k, g_k);
    cudaGetSymbolAddress((void**)&v, g_v);
    cudaGetSymbolAddress((void**)&ctx, g_ctx);
    cudaGetSymbolAddress((void**)&xh, g_xh);
    cudaGetSymbolAddress((void**)&xl, g_xl);
    cudaGetSymbolAddress((void**)&wh, g_wh);
    cudaGetSymbolAddress((void**)&wl, g_wl);

    static int attr_set = -1;
    size_t attn_smem = (size_t)(TR * DH + 32 * 65 + TR * WW) * sizeof(float);
    size_t gemm_smem = 2 * STAGEB;   /* 81920 */
    if (attr_set < 0) {
        cudaFuncSetAttribute(attn_kernel, cudaFuncAttributeMaxDynamicSharedMemorySize, (int)attn_smem);
        cudaFuncSetAttribute(mma_gemm<0>, cudaFuncAttributeMaxDynamicSharedMemorySize, (int)gemm_smem);
        cudaFuncSetAttribute(mma_gemm<1>, cudaFuncAttributeMaxDynamicSharedMemorySize, (int)gemm_smem);
        attr_set = 1;
    }

    split_kernel<<<2048, 256>>>((const float4*)X, (__nv_bfloat162*)xh, (__nv_bfloat162*)xl, MTOT * HID / 4);
    for (int i = 0; i < 4; i++)
        split_kernel<<<1024, 256>>>((const float4*)W[i],
                                    (__nv_bfloat162*)(wh + (size_t)i * HID * HID),
                                    (__nv_bfloat162*)(wl + (size_t)i * HID * HID),
                                    HID * HID / 4);

    dim3 ggrid(HID / 128, MTOT / 128);  /* (8, 32) */
    float* qkv[3] = {q, k, v};
    for (int i = 0; i < 3; i++)
        mma_gemm<0><<<ggrid, 256, gemm_smem>>>(xh, xl,
                                               wh + (size_t)i * HID * HID,
                                               wl + (size_t)i * HID * HID, qkv[i]);

    int write_attn = ((size_t)out_size >= (size_t)OUT_ELEMS + ATTN_ELEMS) ? 1 : 0;
    float* attn_out = write_attn ? (out + OUT_ELEMS) : out;
    dim3 agrid(SS / TR, BB * NH);
    attn_kernel<<<agrid, 256, attn_smem>>>(attn_out, write_attn);

    split_kernel<<<2048, 256>>>((const float4*)ctx, (__nv_bfloat162*)xh, (__nv_bfloat162*)xl, MTOT * HID / 4);
    mma_gemm<1><<<ggrid, 256, gemm_smem>>>(xh, xl,
                                           wh + (size_t)3 * HID * HID,
                                           wl + (size_t)3 * HID * HID, out);
}

// round 5
// speedup vs baseline: 3.2835x; 1.4874x over previous
#include <cuda_runtime.h>
#include <cuda_bf16.h>
#include <cstdint>
#include <math.h>

#define BB 2
#define SS 2048
#define NH 16
#define DH 64
#define HID 1024
#define HALF 256
#define SCALE 0.125f
#define MTOT 4096

#define OUT_ELEMS  (BB*SS*HID)
#define ATTN_ELEMS ((size_t)BB*NH*SS*SS)

/* ---------------- scratch ---------------- */
__device__ __nv_bfloat16 g_xh[MTOT*HID];
__device__ __nv_bfloat16 g_xl[MTOT*HID];
__device__ __nv_bfloat16 g_wh[4][HID*HID];
__device__ __nv_bfloat16 g_wl[4][HID*HID];
__device__ __nv_bfloat16 g_qh[BB*NH*SS*DH];
__device__ __nv_bfloat16 g_ql[BB*NH*SS*DH];
__device__ __nv_bfloat16 g_kh[BB*NH*SS*DH];
__device__ __nv_bfloat16 g_kl[BB*NH*SS*DH];
__device__ __nv_bfloat16 g_vh[BB*NH*SS*DH];
__device__ __nv_bfloat16 g_vl[BB*NH*SS*DH];

/* ---------------- helpers ---------------- */
__device__ __forceinline__ uint32_t smem_u32(const void* p) {
    uint32_t a;
    asm("{ .reg .u64 t; cvta.to.shared.u64 t, %1; cvt.u32.u64 %0, t; }" : "=r"(a) : "l"(p));
    return a;
}
#define CP_ASYNC16(dst, src) asm volatile("cp.async.cg.shared.global [%0], [%1], 16;" :: "r"(dst), "l"(src))
#define CP_COMMIT()          asm volatile("cp.async.commit_group;" ::: "memory")
#define CP_WAIT1()           asm volatile("cp.async.wait_group 1;" ::: "memory")
#define CP_WAIT0()           asm volatile("cp.async.wait_group 0;" ::: "memory")

#define LDMX4(r0,r1,r2,r3,addr) \
    asm volatile("ldmatrix.sync.aligned.m8n8.x4.shared.b16 {%0,%1,%2,%3}, [%4];" \
        : "=r"(r0), "=r"(r1), "=r"(r2), "=r"(r3) : "r"(addr))
#define LDMX2(r0,r1,addr) \
    asm volatile("ldmatrix.sync.aligned.m8n8.x2.shared.b16 {%0,%1}, [%2];" \
        : "=r"(r0), "=r"(r1) : "r"(addr))
#define LDMX2T(r0,r1,addr) \
    asm volatile("ldmatrix.sync.aligned.m8n8.x2.trans.shared.b16 {%0,%1}, [%2];" \
        : "=r"(r0), "=r"(r1) : "r"(addr))

#define MMA16816(c, a, b) \
    asm volatile("mma.sync.aligned.m16n8k16.row.col.f32.bf16.bf16.f32 " \
        "{%0,%1,%2,%3}, {%4,%5,%6,%7}, {%8,%9}, {%0,%1,%2,%3};" \
        : "+f"((c)[0]), "+f"((c)[1]), "+f"((c)[2]), "+f"((c)[3]) \
        : "r"((a)[0]), "r"((a)[1]), "r"((a)[2]), "r"((a)[3]), "r"((b)[0]), "r"((b)[1]))

__device__ __forceinline__ void split2(float x, float y, __nv_bfloat162& hi, __nv_bfloat162& lo) {
    __nv_bfloat16 h0 = __float2bfloat16(x), h1 = __float2bfloat16(y);
    lo = __nv_bfloat162(__float2bfloat16(x - __bfloat162float(h0)),
                        __float2bfloat16(y - __bfloat162float(h1)));
    hi = __nv_bfloat162(h0, h1);
}

/* ---------------- fp32 -> bf16 hi/lo split ---------------- */
__global__ void split_kernel(const float4* __restrict__ src,
                             __nv_bfloat162* __restrict__ hi,
                             __nv_bfloat162* __restrict__ lo, int n4)
{
    for (int i = blockIdx.x * blockDim.x + threadIdx.x; i < n4; i += gridDim.x * blockDim.x) {
        float4 x = src[i];
        __nv_bfloat162 h0, l0, h1, l1;
        split2(x.x, x.y, h0, l0);
        split2(x.z, x.w, h1, l1);
        hi[2*i] = h0; hi[2*i+1] = h1;
        lo[2*i] = l0; lo[2*i+1] = l1;
    }
}

/* ---------------- mma.sync split GEMM (from R4, epilogue variants) ---------------- */
extern __shared__ char dyn_smem[];

#define TROWB 80
#define TILEB (128*TROWB)
#define STAGEB (4*TILEB)

template<int MODE>   /* 0: write bf16 hi/lo qkv layout; 1: fp32 row-major */
__global__ __launch_bounds__(256, 2)
void mma_gemm(const __nv_bfloat16* __restrict__ Ah, const __nv_bfloat16* __restrict__ Al,
              const __nv_bfloat16* __restrict__ Bh, const __nv_bfloat16* __restrict__ Bl,
              float* __restrict__ Y,
              __nv_bfloat16* __restrict__ Yh, __nv_bfloat16* __restrict__ Yl)
{
    uint32_t sb = smem_u32(dyn_smem);
    int tid = threadIdx.x, warp = tid >> 5, lane = tid & 31;
    int warpM = warp >> 2, warpN = warp & 3;
    int bm = blockIdx.y * 128, bn = blockIdx.x * 128;

    float acc[4][4][4];
#pragma unroll
    for (int i = 0; i < 4; i++)
#pragma unroll
        for (int j = 0; j < 4; j++)
#pragma unroll
            for (int t = 0; t < 4; t++) acc[i][j][t] = 0.f;

    const __nv_bfloat16* srcs[4] = {Ah, Al, Bh, Bl};

    auto issue_stage = [&](int s, int k0) {
        uint32_t base = sb + s * STAGEB;
#pragma unroll
        for (int v = 0; v < 8; v++) {
            int idx = tid + v * 256;
            int t = idx >> 9, r = (idx >> 2) & 127, seg = idx & 3;
            int rbase = (t < 2) ? bm : bn;
            const __nv_bfloat16* src = srcs[t] + (size_t)(rbase + r) * 1024 + k0 + seg * 8;
            uint32_t dst = base + t * TILEB + r * TROWB + seg * 16;
            CP_ASYNC16(dst, src);
        }
        CP_COMMIT();
    };

    uint32_t aRowOff = (uint32_t)((warpM * 64 + (lane & 7) + ((lane >> 3) & 1) * 8) * TROWB
                                  + ((lane >> 4) * 8) * 2);
    uint32_t bRowOff = (uint32_t)((warpN * 32 + (lane & 7)) * TROWB
                                  + (((lane >> 3) & 1) * 8) * 2);

    issue_stage(0, 0);

    for (int it = 0; it < 32; it++) {
        if (it + 1 < 32) issue_stage((it + 1) & 1, (it + 1) * 32);
        if (it + 1 < 32) CP_WAIT1(); else CP_WAIT0();
        __syncthreads();

        uint32_t st = sb + (it & 1) * STAGEB;
        uint32_t ah_b = st + aRowOff;
        uint32_t al_b = st + TILEB + aRowOff;
        uint32_t bh_b = st + 2 * TILEB + bRowOff;
        uint32_t bl_b = st + 3 * TILEB + bRowOff;

#pragma unroll
        for (int ks = 0; ks < 2; ks++) {
            uint32_t ko = ks * 32;
            uint32_t aH[4][4], aL[4][4], bb[4][2];
#pragma unroll
            for (int mt = 0; mt < 4; mt++)
                LDMX4(aH[mt][0], aH[mt][1], aH[mt][2], aH[mt][3], ah_b + mt * (16 * TROWB) + ko);
#pragma unroll
            for (int nt = 0; nt < 4; nt++)
                LDMX2(bb[nt][0], bb[nt][1], bh_b + nt * (8 * TROWB) + ko);
#pragma unroll
            for (int mt = 0; mt < 4; mt++)
#pragma unroll
                for (int nt = 0; nt < 4; nt++)
                    MMA16816(acc[mt][nt], aH[mt], bb[nt]);
#pragma unroll
            for (int mt = 0; mt < 4; mt++)
                LDMX4(aL[mt][0], aL[mt][1], aL[mt][2], aL[mt][3], al_b + mt * (16 * TROWB) + ko);
#pragma unroll
            for (int mt = 0; mt < 4; mt++)
#pragma unroll
                for (int nt = 0; nt < 4; nt++)
                    MMA16816(acc[mt][nt], aL[mt], bb[nt]);
#pragma unroll
            for (int nt = 0; nt < 4; nt++)
                LDMX2(bb[nt][0], bb[nt][1], bl_b + nt * (8 * TROWB) + ko);
#pragma unroll
            for (int mt = 0; mt < 4; mt++)
#pragma unroll
                for (int nt = 0; nt < 4; nt++)
                    MMA16816(acc[mt][nt], aH[mt], bb[nt]);
        }
        __syncthreads();
    }

    int row0 = lane >> 2, col0 = (lane & 3) * 2;
#pragma unroll
    for (int mt = 0; mt < 4; mt++) {
#pragma unroll
        for (int half = 0; half < 2; half++) {
            int m = bm + warpM * 64 + mt * 16 + row0 + half * 8;
            int b = m >> 11, s = m & 2047;
#pragma unroll
            for (int nt = 0; nt < 4; nt++) {
                int n = bn + warpN * 32 + nt * 8 + col0;
                float x0 = acc[mt][nt][half * 2 + 0];
                float x1 = acc[mt][nt][half * 2 + 1];
                if (MODE == 0) {
                    int h = n >> 6, d0 = n & 63;
                    size_t idx = (((size_t)b * NH + h) * SS + s) * DH + d0;
                    __nv_bfloat162 hi, lo;
                    split2(x0, x1, hi, lo);
                    *(__nv_bfloat162*)(Yh + idx) = hi;
                    *(__nv_bfloat162*)(Yl + idx) = lo;
                } else {
                    float2 v2; v2.x = x0; v2.y = x1;
                    *(float2*)(Y + (size_t)m * HID + n) = v2;
                }
            }
        }
    }
}

/* ---------------- tensor-core sliding-window attention ----------------
 * Block: 32 query rows of one (b,h), 256 threads (8 warps), window 544 cols.
 * smem (bytes): Sh[32][552]b16 @0 (35328), Sl @35328, Qh @70656 (4608),
 *               Ql @75264, KV dbuf @79872 (2 x (h 4608 + l 4608)) -> total 98304.
 */
#define WW 544
#define SSTR 552
#define OSH 0u
#define OSL 35328u
#define OQH 70656u
#define OQL 75264u
#define OKV 79872u
#define ATTN_SMEM 98304

__global__ __launch_bounds__(256, 2)
void attn_kernel(float* __restrict__ attn_out, int write_attn)
{
    char* sm = dyn_smem;
    uint32_t sb = smem_u32(sm);
    int tid = threadIdx.x, warp = tid >> 5, lane = tid & 31;
    int bh = blockIdx.y;
    int i0 = blockIdx.x * 32;
    int b = bh >> 4, h = bh & 15;
    size_t base = (size_t)bh * SS * DH;
    const __nv_bfloat16 *Qh = g_qh + base, *Ql = g_ql + base;
    const __nv_bfloat16 *Kh = g_kh + base, *Kl = g_kl + base;
    const __nv_bfloat16 *Vh = g_vh + base, *Vl = g_vl + base;
    int jlo = i0 - HALF;

    /* load Q hi/lo tile: 32x64, one uint4 (8 bf16) per thread per matrix */
    {
        int row = tid >> 3, seg = tid & 7;
        uint4 vh4 = *(const uint4*)(Qh + (size_t)(i0 + row) * DH + seg * 8);
        uint4 vl4 = *(const uint4*)(Ql + (size_t)(i0 + row) * DH + seg * 8);
        *(uint4*)(sm + OQH + row * 144 + seg * 16) = vh4;
        *(uint4*)(sm + OQL + row * 144 + seg * 16) = vl4;
    }

    auto load_chunk = [&](const __nv_bfloat16* Mh, const __nv_bfloat16* Ml, int c, int buf) {
#pragma unroll
        for (int u = 0; u < 2; u++) {
            int idx = tid + u * 256;
            int hl = idx >> 8, r = (idx >> 3) & 31, seg = idx & 7;
            int j = jlo + c * 32 + r;
            j = (j < 0) ? 0 : ((j > SS - 1) ? SS - 1 : j);
            const __nv_bfloat16* src = (hl ? Ml : Mh) + (size_t)j * DH + seg * 8;
            uint32_t dst = sb + OKV + buf * 9216 + hl * 4608 + r * 144 + seg * 16;
            CP_ASYNC16(dst, src);
        }
        CP_COMMIT();
    };

    /* ---------- phase 1: scores ---------- */
    {
        int mt = warp >> 2, nt = warp & 3;
        uint32_t aoffQ = (uint32_t)((mt * 16 + (lane & 15)) * 144 + (lane >> 4) * 16);
        uint32_t boffK = (uint32_t)((nt * 8 + (lane & 7)) * 144 + ((lane >> 3) & 1) * 16);
        load_chunk(Kh, Kl, 0, 0);
        for (int c = 0; c < 17; c++) {
            if (c + 1 < 17) { load_chunk(Kh, Kl, c + 1, (c + 1) & 1); CP_WAIT1(); }
            else CP_WAIT0();
            __syncthreads();
            uint32_t kb = sb + OKV + (c & 1) * 9216;
            float acc[4] = {0.f, 0.f, 0.f, 0.f};
#pragma unroll
            for (int ks = 0; ks < 4; ks++) {
                uint32_t aH[4], aL[4], bH[2], bL[2];
                LDMX4(aH[0], aH[1], aH[2], aH[3], sb + OQH + aoffQ + ks * 32);
                LDMX4(aL[0], aL[1], aL[2], aL[3], sb + OQL + aoffQ + ks * 32);
                LDMX2(bH[0], bH[1], kb + boffK + ks * 32);
                LDMX2(bL[0], bL[1], kb + 4608 + boffK + ks * 32);
                MMA16816(acc, aH, bH);
                MMA16816(acc, aL, bH);
                MMA16816(acc, aH, bL);
            }
            int colb = c * 32 + nt * 8 + (lane & 3) * 2;
#pragma unroll
            for (int half = 0; half < 2; half++) {
                int r = mt * 16 + (lane >> 2) + half * 8;
                int i = i0 + r;
                int j0 = jlo + colb, j1 = j0 + 1;
                float s0 = acc[half * 2 + 0] * SCALE;
                float s1 = acc[half * 2 + 1] * SCALE;
                if (!((j0 >= 0) && (j0 < SS) && (j0 >= i - HALF) && (j0 <= i + HALF))) s0 = -1e30f;
                if (!((j1 >= 0) && (j1 < SS) && (j1 >= i - HALF) && (j1 <= i + HALF))) s1 = -1e30f;
                __nv_bfloat162 hi, lo;
                split2(s0, s1, hi, lo);
                *(__nv_bfloat162*)(sm + OSH + (r * SSTR + colb) * 2) = hi;
                *(__nv_bfloat162*)(sm + OSL + (r * SSTR + colb) * 2) = lo;
            }
            __syncthreads();
        }
    }

    /* ---------- phase 2: softmax (warp: rows warp*4 .. warp*4+3), P stored hi/lo in place ---------- */
    {
        for (int rr = 0; rr < 4; rr++) {
            int r = warp * 4 + rr;
            uint32_t rh = OSH + r * SSTR * 2, rl = OSL + r * SSTR * 2;
            float mx = -1e30f;
            for (int pc = lane; pc < 272; pc += 32) {
                __nv_bfloat162 hh = *(__nv_bfloat162*)(sm + rh + pc * 4);
                __nv_bfloat162 ll = *(__nv_bfloat162*)(sm + rl + pc * 4);
                float s0 = __bfloat162float(hh.x) + __bfloat162float(ll.x);
                float s1 = __bfloat162float(hh.y) + __bfloat162float(ll.y);
                mx = fmaxf(mx, fmaxf(s0, s1));
            }
#pragma unroll
            for (int o = 16; o > 0; o >>= 1) mx = fmaxf(mx, __shfl_xor_sync(0xffffffffu, mx, o));
            float sum = 0.f;
            for (int pc = lane; pc < 272; pc += 32) {
                __nv_bfloat162 hh = *(__nv_bfloat162*)(sm + rh + pc * 4);
                __nv_bfloat162 ll = *(__nv_bfloat162*)(sm + rl + pc * 4);
                float s0 = __bfloat162float(hh.x) + __bfloat162float(ll.x);
                float s1 = __bfloat162float(hh.y) + __bfloat162float(ll.y);
                sum += __expf(s0 - mx) + __expf(s1 - mx);
            }
#pragma unroll
            for (int o = 16; o > 0; o >>= 1) sum += __shfl_xor_sync(0xffffffffu, sum, o);
            float inv = 1.f / sum;
            for (int pc = lane; pc < 272; pc += 32) {
                __nv_bfloat162 hh = *(__nv_bfloat162*)(sm + rh + pc * 4);
                __nv_bfloat162 ll = *(__nv_bfloat162*)(sm + rl + pc * 4);
                float s0 = __bfloat162float(hh.x) + __bfloat162float(ll.x);
                float s1 = __bfloat162float(hh.y) + __bfloat162float(ll.y);
                float p0 = __expf(s0 - mx) * inv;
                float p1 = __expf(s1 - mx) * inv;
                __nv_bfloat162 hi, lo;
                split2(p0, p1, hi, lo);
                *(__nv_bfloat162*)(sm + rh + pc * 4) = hi;
                *(__nv_bfloat162*)(sm + rl + pc * 4) = lo;
            }
        }
        __syncthreads();
    }

    /* ---------- phase 2.5: write attn tensor ---------- */
    if (write_attn) {
        for (int rr = 0; rr < 4; rr++) {
            int r = warp * 4 + rr;
            int i = i0 + r;
            float* row = attn_out + ((size_t)bh * SS + i) * SS;
            uint32_t rh = OSH + r * SSTR * 2, rl = OSL + r * SSTR * 2;
            for (int j4 = lane * 4; j4 < SS; j4 += 128) {
                float4 v4;
                float* vv = (float*)&v4;
#pragma unroll
                for (int e = 0; e < 4; e++) {
                    int cidx = j4 + e - jlo;
                    float p = 0.f;
                    if (cidx >= 0 && cidx < WW) {
                        __nv_bfloat16 ph = *(__nv_bfloat16*)(sm + rh + cidx * 2);
                        __nv_bfloat16 pl = *(__nv_bfloat16*)(sm + rl + cidx * 2);
                        p = __bfloat162float(ph) + __bfloat162float(pl);
                    }
                    vv[e] = p;
                }
                *(float4*)(row + j4) = v4;
            }
        }
    }

    /* ---------- phase 3: PV ---------- */
    {
        int mtp = warp >> 2;            /* 0..1 */
        int ntb = (warp & 3) * 2;       /* n-tile base, tiles ntb, ntb+1 */
        float oacc[2][4];
#pragma unroll
        for (int p = 0; p < 2; p++)
#pragma unroll
            for (int t = 0; t < 4; t++) oacc[p][t] = 0.f;

        uint32_t aoffP = (uint32_t)((mtp * 16 + (lane & 15)) * SSTR * 2 + (lane >> 4) * 16);
        uint32_t vrow = (uint32_t)(((lane & 7) + ((lane >> 3) & 1) * 8) * 144);

        load_chunk(Vh, Vl, 0, 0);
        for (int c = 0; c < 17; c++) {
            if (c + 1 < 17) { load_chunk(Vh, Vl, c + 1, (c + 1) & 1); CP_WAIT1(); }
            else CP_WAIT0();
            __syncthreads();
            uint32_t vb = sb + OKV + (c & 1) * 9216;
#pragma unroll
            for (int ks = 0; ks < 2; ks++) {
                uint32_t aH[4], aL[4];
                LDMX4(aH[0], aH[1], aH[2], aH[3], sb + OSH + aoffP + (c * 32 + ks * 16) * 2);
                LDMX4(aL[0], aL[1], aL[2], aL[3], sb + OSL + aoffP + (c * 32 + ks * 16) * 2);
#pragma unroll
                for (int p = 0; p < 2; p++) {
                    int nt = ntb + p;
                    uint32_t bH[2], bL[2];
                    uint32_t va = vb + vrow + ks * 16 * 144 + nt * 16;
                    LDMX2T(bH[0], bH[1], va);
                    LDMX2T(bL[0], bL[1], va + 4608);
                    MMA16816(oacc[p], aH, bH);
                    MMA16816(oacc[p], aL, bH);
                    MMA16816(oacc[p], aH, bL);
                }
            }
            __syncthreads();
        }

        /* ---------- phase 4: write ctx directly as bf16 hi/lo into g_xh/g_xl ---------- */
        int row0 = lane >> 2, col0 = (lane & 3) * 2;
#pragma unroll
        for (int p = 0; p < 2; p++) {
            int nt = ntb + p;
#pragma unroll
            for (int half = 0; half < 2; half++) {
                int i = i0 + mtp * 16 + row0 + half * 8;
                size_t m = (size_t)b * SS + i;
                int d = nt * 8 + col0;
                float x0 = oacc[p][half * 2 + 0];
                float x1 = oacc[p][half * 2 + 1];
                __nv_bfloat162 hi, lo;
                split2(x0, x1, hi, lo);
                size_t idx = m * HID + h * DH + d;
                *(__nv_bfloat162*)(g_xh + idx) = hi;
                *(__nv_bfloat162*)(g_xl + idx) = lo;
            }
        }
    }
}

/* ---------------- launch ---------------- */
extern "C" void kernel_launch(void* const* d_in, const int* in_sizes, int n_in,
                              void* d_out, int out_size)
{
    const float* X = (const float*)d_in[0];
    const float* W[4] = {(const float*)d_in[1], (const float*)d_in[2],
                         (const float*)d_in[3], (const float*)d_in[4]};
    float* out = (float*)d_out;

    __nv_bfloat16 *xh, *xl, *wh, *wl, *qh, *ql, *kh, *kl, *vh, *vl;
    cudaGetSymbolAddress((void**)&xh, g_xh);
    cudaGetSymbolAddress((void**)&xl, g_xl);
    cudaGetSymbolAddress((void**)&wh, g_wh);
    cudaGetSymbolAddress((void**)&wl, g_wl);
    cudaGetSymbolAddress((void**)&qh, g_qh);
    cudaGetSymbolAddress((void**)&ql, g_ql);
    cudaGetSymbolAddress((void**)&kh, g_kh);
    cudaGetSymbolAddress((void**)&kl, g_kl);
    cudaGetSymbolAddress((void**)&vh, g_vh);
    cudaGetSymbolAddress((void**)&vl, g_vl);

    static int attr_set = -1;
    size_t gemm_smem = 2 * STAGEB;
    if (attr_set < 0) {
        cudaFuncSetAttribute(attn_kernel, cudaFuncAttributeMaxDynamicSharedMemorySize, ATTN_SMEM);
        cudaFuncSetAttribute(mma_gemm<0>, cudaFuncAttributeMaxDynamicSharedMemorySize, (int)gemm_smem);
        cudaFuncSetAttribute(mma_gemm<1>, cudaFuncAttributeMaxDynamicSharedMemorySize, (int)gemm_smem);
        attr_set = 1;
    }

    split_kernel<<<2048, 256>>>((const float4*)X, (__nv_bfloat162*)xh, (__nv_bfloat162*)xl, MTOT * HID / 4);
    for (int i = 0; i < 4; i++)
        split_kernel<<<1024, 256>>>((const float4*)W[i],
                                    (__nv_bfloat162*)(wh + (size_t)i * HID * HID),
                                    (__nv_bfloat162*)(wl + (size_t)i * HID * HID),
                                    HID * HID / 4);

    dim3 ggrid(HID / 128, MTOT / 128);
    __nv_bfloat16* outs[3][2] = {{qh, ql}, {kh, kl}, {vh, vl}};
    for (int i = 0; i < 3; i++)
        mma_gemm<0><<<ggrid, 256, gemm_smem>>>(xh, xl,
                                               wh + (size_t)i * HID * HID,
                                               wl + (size_t)i * HID * HID,
                                               nullptr, outs[i][0], outs[i][1]);

    int write_attn = ((size_t)out_size >= (size_t)OUT_ELEMS + ATTN_ELEMS) ? 1 : 0;
    float* attn_out = write_attn ? (out + OUT_ELEMS) : out;
    dim3 agrid(SS / 32, BB * NH);
    attn_kernel<<<agrid, 256, ATTN_SMEM>>>(attn_out, write_attn);

    mma_gemm<1><<<ggrid, 256, gemm_smem>>>(xh, xl,
                                           wh + (size_t)3 * HID * HID,
                                           wl + (size_t)3 * HID * HID,
                                           out, nullptr, nullptr);
}

// round 7
// speedup vs baseline: 3.5934x; 1.0944x over previous
#include <cuda_runtime.h>
#include <cuda_bf16.h>
#include <cstdint>
#include <math.h>

#define BB 2
#define SS 2048
#define NH 16
#define DH 64
#define HID 1024
#define HALF 256
#define SCALE 0.125f
#define MTOT 4096

#define OUT_ELEMS  (BB*SS*HID)
#define ATTN_ELEMS ((size_t)BB*NH*SS*SS)

/* ---------------- scratch ---------------- */
__device__ __nv_bfloat16 g_xh[MTOT*HID];
__device__ __nv_bfloat16 g_xl[MTOT*HID];
__device__ __nv_bfloat16 g_wh[4][HID*HID];
__device__ __nv_bfloat16 g_wl[4][HID*HID];
__device__ __nv_bfloat16 g_qh[BB*NH*SS*DH];
__device__ __nv_bfloat16 g_ql[BB*NH*SS*DH];
__device__ __nv_bfloat16 g_kh[BB*NH*SS*DH];
__device__ __nv_bfloat16 g_kl[BB*NH*SS*DH];
__device__ __nv_bfloat16 g_vh[BB*NH*SS*DH];
__device__ __nv_bfloat16 g_vl[BB*NH*SS*DH];

/* ---------------- helpers ---------------- */
__device__ __forceinline__ uint32_t smem_u32(const void* p) {
    uint32_t a;
    asm("{ .reg .u64 t; cvta.to.shared.u64 t, %1; cvt.u32.u64 %0, t; }" : "=r"(a) : "l"(p));
    return a;
}
#define CP_ASYNC16(dst, src) asm volatile("cp.async.cg.shared.global [%0], [%1], 16;" :: "r"(dst), "l"(src))
#define CP_COMMIT()          asm volatile("cp.async.commit_group;" ::: "memory")
#define CP_WAIT1()           asm volatile("cp.async.wait_group 1;" ::: "memory")
#define CP_WAIT0()           asm volatile("cp.async.wait_group 0;" ::: "memory")

#define LDMX4(r0,r1,r2,r3,addr) \
    asm volatile("ldmatrix.sync.aligned.m8n8.x4.shared.b16 {%0,%1,%2,%3}, [%4];" \
        : "=r"(r0), "=r"(r1), "=r"(r2), "=r"(r3) : "r"(addr))
#define LDMX4T(r0,r1,r2,r3,addr) \
    asm volatile("ldmatrix.sync.aligned.m8n8.x4.trans.shared.b16 {%0,%1,%2,%3}, [%4];" \
        : "=r"(r0), "=r"(r1), "=r"(r2), "=r"(r3) : "r"(addr))

#define MMA16816(c, a, b) \
    asm volatile("mma.sync.aligned.m16n8k16.row.col.f32.bf16.bf16.f32 " \
        "{%0,%1,%2,%3}, {%4,%5,%6,%7}, {%8,%9}, {%0,%1,%2,%3};" \
        : "+f"((c)[0]), "+f"((c)[1]), "+f"((c)[2]), "+f"((c)[3]) \
        : "r"((a)[0]), "r"((a)[1]), "r"((a)[2]), "r"((a)[3]), "r"((b)[0]), "r"((b)[1]))

__device__ __forceinline__ void split2(float x, float y, __nv_bfloat162& hi, __nv_bfloat162& lo) {
    __nv_bfloat16 h0 = __float2bfloat16(x), h1 = __float2bfloat16(y);
    lo = __nv_bfloat162(__float2bfloat16(x - __bfloat162float(h0)),
                        __float2bfloat16(y - __bfloat162float(h1)));
    hi = __nv_bfloat162(h0, h1);
}

/* ---------------- fused fp32 -> bf16 hi/lo split (X + 4 weights) ---------------- */
__global__ void split_multi(const float4* __restrict__ X,
                            const float4* __restrict__ W0, const float4* __restrict__ W1,
                            const float4* __restrict__ W2, const float4* __restrict__ W3,
                            __nv_bfloat162* __restrict__ xh, __nv_bfloat162* __restrict__ xl,
                            __nv_bfloat162* __restrict__ wh, __nv_bfloat162* __restrict__ wl)
{
    int r = blockIdx.y;
    const float4* src;
    __nv_bfloat162 *hi, *lo;
    int n4;
    if (r == 0) { src = X; hi = xh; lo = xl; n4 = MTOT * HID / 4; }
    else {
        src = (r == 1) ? W0 : (r == 2) ? W1 : (r == 3) ? W2 : W3;
        hi = wh + (size_t)(r - 1) * (HID * HID / 2);
        lo = wl + (size_t)(r - 1) * (HID * HID / 2);
        n4 = HID * HID / 4;
    }
    for (int i = blockIdx.x * blockDim.x + threadIdx.x; i < n4; i += gridDim.x * blockDim.x) {
        float4 x = src[i];
        __nv_bfloat162 h0, l0, h1, l1;
        split2(x.x, x.y, h0, l0);
        split2(x.z, x.w, h1, l1);
        hi[2*i] = h0; hi[2*i+1] = h1;
        lo[2*i] = l0; lo[2*i+1] = l1;
    }
}

/* ---------------- mma.sync split GEMM ----------------
 * MODE 0: fused QKV (grid.x=24, N=3072 concat weights), writes bf16 hi/lo qkv layout.
 * MODE 1: out-proj (grid.x=8), fp32 row-major out.
 */
extern __shared__ char dyn_smem[];

#define TROWB 80
#define TILEB (128*TROWB)
#define STAGEB (4*TILEB)

template<int MODE>
__global__ __launch_bounds__(256, 2)
void mma_gemm(const __nv_bfloat16* __restrict__ Ah, const __nv_bfloat16* __restrict__ Al,
              const __nv_bfloat16* __restrict__ Bh, const __nv_bfloat16* __restrict__ Bl,
              float* __restrict__ Y,
              __nv_bfloat16* __restrict__ qh, __nv_bfloat16* __restrict__ ql,
              __nv_bfloat16* __restrict__ kh, __nv_bfloat16* __restrict__ kl,
              __nv_bfloat16* __restrict__ vh, __nv_bfloat16* __restrict__ vl)
{
    uint32_t sb = smem_u32(dyn_smem);
    int tid = threadIdx.x, warp = tid >> 5, lane = tid & 31;
    int warpM = warp >> 2, warpN = warp & 3;
    int bm = blockIdx.y * 128, bn = blockIdx.x * 128;

    float acc[4][4][4];
#pragma unroll
    for (int i = 0; i < 4; i++)
#pragma unroll
        for (int j = 0; j < 4; j++)
#pragma unroll
            for (int t = 0; t < 4; t++) acc[i][j][t] = 0.f;

    const __nv_bfloat16* srcs[4] = {Ah, Al, Bh, Bl};

    auto issue_stage = [&](int s, int k0) {
        uint32_t base = sb + s * STAGEB;
#pragma unroll
        for (int v = 0; v < 8; v++) {
            int idx = tid + v * 256;
            int t = idx >> 9, r = (idx >> 2) & 127, seg = idx & 3;
            int rbase = (t < 2) ? bm : bn;
            const __nv_bfloat16* src = srcs[t] + (size_t)(rbase + r) * 1024 + k0 + seg * 8;
            uint32_t dst = base + t * TILEB + r * TROWB + seg * 16;
            CP_ASYNC16(dst, src);
        }
        CP_COMMIT();
    };

    uint32_t aRowOff = (uint32_t)((warpM * 64 + (lane & 7) + ((lane >> 3) & 1) * 8) * TROWB
                                  + ((lane >> 4) * 8) * 2);
    /* B x4-paired: rows (lane&7)+((lane>>4)&1)*8 of a 16-row pair, col half (lane>>3)&1 */
    uint32_t bRowOff4 = (uint32_t)((warpN * 32 + (lane & 7) + ((lane >> 4) & 1) * 8) * TROWB
                                   + ((lane >> 3) & 1) * 16);

    issue_stage(0, 0);

    for (int it = 0; it < 32; it++) {
        if (it + 1 < 32) issue_stage((it + 1) & 1, (it + 1) * 32);
        if (it + 1 < 32) CP_WAIT1(); else CP_WAIT0();
        __syncthreads();

        uint32_t st = sb + (it & 1) * STAGEB;
        uint32_t ah_b = st + aRowOff;
        uint32_t al_b = st + TILEB + aRowOff;
        uint32_t bh_b = st + 2 * TILEB + bRowOff4;
        uint32_t bl_b = st + 3 * TILEB + bRowOff4;

#pragma unroll
        for (int ks = 0; ks < 2; ks++) {
            uint32_t ko = ks * 32;
            uint32_t aH[4][4], aL[4][4], bb[4][2];
#pragma unroll
            for (int mt = 0; mt < 4; mt++)
                LDMX4(aH[mt][0], aH[mt][1], aH[mt][2], aH[mt][3], ah_b + mt * (16 * TROWB) + ko);
            LDMX4(bb[0][0], bb[0][1], bb[1][0], bb[1][1], bh_b + ko);
            LDMX4(bb[2][0], bb[2][1], bb[3][0], bb[3][1], bh_b + 16 * TROWB + ko);
#pragma unroll
            for (int mt = 0; mt < 4; mt++)
#pragma unroll
                for (int nt = 0; nt < 4; nt++)
                    MMA16816(acc[mt][nt], aH[mt], bb[nt]);
#pragma unroll
            for (int mt = 0; mt < 4; mt++)
                LDMX4(aL[mt][0], aL[mt][1], aL[mt][2], aL[mt][3], al_b + mt * (16 * TROWB) + ko);
#pragma unroll
            for (int mt = 0; mt < 4; mt++)
#pragma unroll
                for (int nt = 0; nt < 4; nt++)
                    MMA16816(acc[mt][nt], aL[mt], bb[nt]);
            LDMX4(bb[0][0], bb[0][1], bb[1][0], bb[1][1], bl_b + ko);
            LDMX4(bb[2][0], bb[2][1], bb[3][0], bb[3][1], bl_b + 16 * TROWB + ko);
#pragma unroll
            for (int mt = 0; mt < 4; mt++)
#pragma unroll
                for (int nt = 0; nt < 4; nt++)
                    MMA16816(acc[mt][nt], aH[mt], bb[nt]);
        }
        __syncthreads();
    }

    int row0 = lane >> 2, col0 = (lane & 3) * 2;
    __nv_bfloat16 *Yh = nullptr, *Yl = nullptr;
    int nbase = 0;
    if (MODE == 0) {
        int mat = blockIdx.x >> 3;
        Yh = (mat == 0) ? qh : ((mat == 1) ? kh : vh);
        Yl = (mat == 0) ? ql : ((mat == 1) ? kl : vl);
        nbase = (blockIdx.x & 7) * 128;
    }
#pragma unroll
    for (int mt = 0; mt < 4; mt++) {
#pragma unroll
        for (int half = 0; half < 2; half++) {
            int m = bm + warpM * 64 + mt * 16 + row0 + half * 8;
            int b = m >> 11, s = m & 2047;
#pragma unroll
            for (int nt = 0; nt < 4; nt++) {
                float x0 = acc[mt][nt][half * 2 + 0];
                float x1 = acc[mt][nt][half * 2 + 1];
                if (MODE == 0) {
                    int n = nbase + warpN * 32 + nt * 8 + col0;
                    int h = n >> 6, d0 = n & 63;
                    size_t idx = (((size_t)b * NH + h) * SS + s) * DH + d0;
                    __nv_bfloat162 hi, lo;
                    split2(x0, x1, hi, lo);
                    *(__nv_bfloat162*)(Yh + idx) = hi;
                    *(__nv_bfloat162*)(Yl + idx) = lo;
                } else {
                    int n = bn + warpN * 32 + nt * 8 + col0;
                    float2 v2; v2.x = x0; v2.y = x1;
                    *(float2*)(Y + (size_t)m * HID + n) = v2;
                }
            }
        }
    }
}

/* ---------------- tensor-core sliding-window attention ----------------
 * 32 query rows/block, 256 threads (8 warps), window 544 cols.
 * smem: Sh @0 (35328), Sl @35328, Qh @70656 (4608), Ql @75264 (4608),
 *       KV triple-buffer @79872 (3 x 9216) -> total 107520.
 */
#define WW 544
#define SSTR 552
#define OSH 0u
#define OSL 35328u
#define OQH 70656u
#define OQL 75264u
#define OKV 79872u
#define ATTN_SMEM 107520

__global__ __launch_bounds__(256, 2)
void attn_kernel(float* __restrict__ attn_out, int write_attn)
{
    char* sm = dyn_smem;
    uint32_t sb = smem_u32(sm);
    int tid = threadIdx.x, warp = tid >> 5, lane = tid & 31;
    int bh = blockIdx.y;
    int i0 = blockIdx.x * 32;
    int b = bh >> 4, h = bh & 15;
    size_t base = (size_t)bh * SS * DH;
    const __nv_bfloat16 *Qh = g_qh + base, *Ql = g_ql + base;
    const __nv_bfloat16 *Kh = g_kh + base, *Kl = g_kl + base;
    const __nv_bfloat16 *Vh = g_vh + base, *Vl = g_vl + base;
    int jlo = i0 - HALF;

    /* load Q hi/lo tile: 32x64 */
    {
        int row = tid >> 3, seg = tid & 7;
        uint4 vh4 = *(const uint4*)(Qh + (size_t)(i0 + row) * DH + seg * 8);
        uint4 vl4 = *(const uint4*)(Ql + (size_t)(i0 + row) * DH + seg * 8);
        *(uint4*)(sm + OQH + row * 144 + seg * 16) = vh4;
        *(uint4*)(sm + OQL + row * 144 + seg * 16) = vl4;
    }

    auto load_chunk = [&](const __nv_bfloat16* Mh, const __nv_bfloat16* Ml, int c, int buf) {
#pragma unroll
        for (int u = 0; u < 2; u++) {
            int idx = tid + u * 256;
            int hl = idx >> 8, r = (idx >> 3) & 31, seg = idx & 7;
            int j = jlo + c * 32 + r;
            j = (j < 0) ? 0 : ((j > SS - 1) ? SS - 1 : j);
            const __nv_bfloat16* src = (hl ? Ml : Mh) + (size_t)j * DH + seg * 8;
            uint32_t dst = sb + OKV + buf * 9216 + hl * 4608 + r * 144 + seg * 16;
            CP_ASYNC16(dst, src);
        }
        CP_COMMIT();
    };

    /* ---------- phase 1: scores ---------- */
    {
        int mt = warp >> 2, nt = warp & 3;
        uint32_t aoffQ = (uint32_t)((mt * 16 + (lane & 15)) * 144 + (lane >> 4) * 16);
        /* B x4 over 4 ks: rows (lane&7), col quarter (lane>>3)&3 */
        uint32_t boffK4 = (uint32_t)((nt * 8 + (lane & 7)) * 144 + ((lane >> 3) & 3) * 16);

        load_chunk(Kh, Kl, 0, 0);
        __syncthreads();            /* Q visible to all */

        /* hoist Q fragments (invariant over chunks) */
        uint32_t qHf[4][4], qLf[4][4];
#pragma unroll
        for (int ks = 0; ks < 4; ks++) {
            LDMX4(qHf[ks][0], qHf[ks][1], qHf[ks][2], qHf[ks][3], sb + OQH + aoffQ + ks * 32);
            LDMX4(qLf[ks][0], qLf[ks][1], qLf[ks][2], qLf[ks][3], sb + OQL + aoffQ + ks * 32);
        }

        for (int c = 0; c < 17; c++) {
            if (c + 1 < 17) { load_chunk(Kh, Kl, c + 1, (c + 1) % 3); CP_WAIT1(); }
            else CP_WAIT0();
            __syncthreads();
            uint32_t kb = sb + OKV + (c % 3) * 9216;
            float acc[4] = {0.f, 0.f, 0.f, 0.f};
            uint32_t bHf[4][2], bLf[4][2];
            LDMX4(bHf[0][0], bHf[0][1], bHf[1][0], bHf[1][1], kb + boffK4);
            LDMX4(bHf[2][0], bHf[2][1], bHf[3][0], bHf[3][1], kb + boffK4 + 64);
            LDMX4(bLf[0][0], bLf[0][1], bLf[1][0], bLf[1][1], kb + 4608 + boffK4);
            LDMX4(bLf[2][0], bLf[2][1], bLf[3][0], bLf[3][1], kb + 4608 + boffK4 + 64);
#pragma unroll
            for (int ks = 0; ks < 4; ks++) {
                MMA16816(acc, qHf[ks], bHf[ks]);
                MMA16816(acc, qLf[ks], bHf[ks]);
                MMA16816(acc, qHf[ks], bLf[ks]);
            }
            int colb = c * 32 + nt * 8 + (lane & 3) * 2;
#pragma unroll
            for (int half = 0; half < 2; half++) {
                int r = mt * 16 + (lane >> 2) + half * 8;
                int i = i0 + r;
                int j0 = jlo + colb, j1 = j0 + 1;
                float s0 = acc[half * 2 + 0] * SCALE;
                float s1 = acc[half * 2 + 1] * SCALE;
                if (!((j0 >= 0) && (j0 < SS) && (j0 >= i - HALF) && (j0 <= i + HALF))) s0 = -1e30f;
                if (!((j1 >= 0) && (j1 < SS) && (j1 >= i - HALF) && (j1 <= i + HALF))) s1 = -1e30f;
                __nv_bfloat162 hi, lo;
                split2(s0, s1, hi, lo);
                *(__nv_bfloat162*)(sm + OSH + (r * SSTR + colb) * 2) = hi;
                *(__nv_bfloat162*)(sm + OSL + (r * SSTR + colb) * 2) = lo;
            }
        }
        __syncthreads();
    }

    /* ---------- phase 2: softmax ---------- */
    {
        for (int rr = 0; rr < 4; rr++) {
            int r = warp * 4 + rr;
            uint32_t rh = OSH + r * SSTR * 2, rl = OSL + r * SSTR * 2;
            float mx = -1e30f;
            for (int pc = lane; pc < 272; pc += 32) {
                __nv_bfloat162 hh = *(__nv_bfloat162*)(sm + rh + pc * 4);
                __nv_bfloat162 ll = *(__nv_bfloat162*)(sm + rl + pc * 4);
                float s0 = __bfloat162float(hh.x) + __bfloat162float(ll.x);
                float s1 = __bfloat162float(hh.y) + __bfloat162float(ll.y);
                mx = fmaxf(mx, fmaxf(s0, s1));
            }
#pragma unroll
            for (int o = 16; o > 0; o >>= 1) mx = fmaxf(mx, __shfl_xor_sync(0xffffffffu, mx, o));
            float sum = 0.f;
            for (int pc = lane; pc < 272; pc += 32) {
                __nv_bfloat162 hh = *(__nv_bfloat162*)(sm + rh + pc * 4);
                __nv_bfloat162 ll = *(__nv_bfloat162*)(sm + rl + pc * 4);
                float s0 = __bfloat162float(hh.x) + __bfloat162float(ll.x);
                float s1 = __bfloat162float(hh.y) + __bfloat162float(ll.y);
                sum += __expf(s0 - mx) + __expf(s1 - mx);
            }
#pragma unroll
            for (int o = 16; o > 0; o >>= 1) sum += __shfl_xor_sync(0xffffffffu, sum, o);
            float inv = 1.f / sum;
            for (int pc = lane; pc < 272; pc += 32) {
                __nv_bfloat162 hh = *(__nv_bfloat162*)(sm + rh + pc * 4);
                __nv_bfloat162 ll = *(__nv_bfloat162*)(sm + rl + pc * 4);
                float s0 = __bfloat162float(hh.x) + __bfloat162float(ll.x);
                float s1 = __bfloat162float(hh.y) + __bfloat162float(ll.y);
                float p0 = __expf(s0 - mx) * inv;
                float p1 = __expf(s1 - mx) * inv;
                __nv_bfloat162 hi, lo;
                split2(p0, p1, hi, lo);
                *(__nv_bfloat162*)(sm + rh + pc * 4) = hi;
                *(__nv_bfloat162*)(sm + rl + pc * 4) = lo;
            }
        }
        __syncthreads();
    }

    /* ---------- phase 2.5: write attn tensor ---------- */
    if (write_attn) {
        for (int rr = 0; rr < 4; rr++) {
            int r = warp * 4 + rr;
            int i = i0 + r;
            float* row = attn_out + ((size_t)bh * SS + i) * SS;
            uint32_t rh = OSH + r * SSTR * 2, rl = OSL + r * SSTR * 2;
            for (int j4 = lane * 4; j4 < SS; j4 += 128) {
                float4 v4;
                float* vv = (float*)&v4;
#pragma unroll
                for (int e = 0; e < 4; e++) {
                    int cidx = j4 + e - jlo;
                    float p = 0.f;
                    if (cidx >= 0 && cidx < WW) {
                        __nv_bfloat16 ph = *(__nv_bfloat16*)(sm + rh + cidx * 2);
                        __nv_bfloat16 pl = *(__nv_bfloat16*)(sm + rl + cidx * 2);
                        p = __bfloat162float(ph) + __bfloat162float(pl);
                    }
                    vv[e] = p;
                }
                *(float4*)(row + j4) = v4;
            }
        }
    }

    /* ---------- phase 3: PV ---------- */
    {
        int mtp = warp >> 2;
        int ntb = (warp & 3) * 2;
        float oacc[2][4];
#pragma unroll
        for (int p = 0; p < 2; p++)
#pragma unroll
            for (int t = 0; t < 4; t++) oacc[p][t] = 0.f;

        uint32_t aoffP = (uint32_t)((mtp * 16 + (lane & 15)) * SSTR * 2 + (lane >> 4) * 16);
        /* V x4-trans pairing two nt tiles: rows (lane&7)+((lane>>3)&1)*8, col pair (lane>>4) */
        uint32_t vrow4 = (uint32_t)((((lane & 7) + ((lane >> 3) & 1) * 8)) * 144 + (lane >> 4) * 16);

        load_chunk(Vh, Vl, 0, 0);
        for (int c = 0; c < 17; c++) {
            if (c + 1 < 17) { load_chunk(Vh, Vl, c + 1, (c + 1) % 3); CP_WAIT1(); }
            else CP_WAIT0();
            __syncthreads();
            uint32_t vb = sb + OKV + (c % 3) * 9216;
#pragma unroll
            for (int ks = 0; ks < 2; ks++) {
                uint32_t aH[4], aL[4];
                LDMX4(aH[0], aH[1], aH[2], aH[3], sb + OSH + aoffP + (c * 32 + ks * 16) * 2);
                LDMX4(aL[0], aL[1], aL[2], aL[3], sb + OSL + aoffP + (c * 32 + ks * 16) * 2);
                uint32_t bHf[2][2], bLf[2][2];
                uint32_t va = vb + vrow4 + ks * 16 * 144 + ntb * 16;
                LDMX4T(bHf[0][0], bHf[0][1], bHf[1][0], bHf[1][1], va);
                LDMX4T(bLf[0][0], bLf[0][1], bLf[1][0], bLf[1][1], va + 4608);
#pragma unroll
                for (int p = 0; p < 2; p++) {
                    MMA16816(oacc[p], aH, bHf[p]);
                    MMA16816(oacc[p], aL, bHf[p]);
                    MMA16816(oacc[p], aH, bLf[p]);
                }
            }
        }

        /* write ctx as bf16 hi/lo into g_xh/g_xl */
        int row0 = lane >> 2, col0 = (lane & 3) * 2;
#pragma unroll
        for (int p = 0; p < 2; p++) {
            int nt = ntb + p;
#pragma unroll
            for (int half = 0; half < 2; half++) {
                int i = i0 + mtp * 16 + row0 + half * 8;
                size_t m = (size_t)b * SS + i;
                int d = nt * 8 + col0;
                float x0 = oacc[p][half * 2 + 0];
                float x1 = oacc[p][half * 2 + 1];
                __nv_bfloat162 hi, lo;
                split2(x0, x1, hi, lo);
                size_t idx = m * HID + h * DH + d;
                *(__nv_bfloat162*)(g_xh + idx) = hi;
                *(__nv_bfloat162*)(g_xl + idx) = lo;
            }
        }
    }
}

/* ---------------- launch ---------------- */
extern "C" void kernel_launch(void* const* d_in, const int* in_sizes, int n_in,
                              void* d_out, int out_size)
{
    const float* X = (const float*)d_in[0];
    const float* W[4] = {(const float*)d_in[1], (const float*)d_in[2],
                         (const float*)d_in[3], (const float*)d_in[4]};
    float* out = (float*)d_out;

    __nv_bfloat16 *xh, *xl, *wh, *wl, *qh, *ql, *kh, *kl, *vh, *vl;
    cudaGetSymbolAddress((void**)&xh, g_xh);
    cudaGetSymbolAddress((void**)&xl, g_xl);
    cudaGetSymbolAddress((void**)&wh, g_wh);
    cudaGetSymbolAddress((void**)&wl, g_wl);
    cudaGetSymbolAddress((void**)&qh, g_qh);
    cudaGetSymbolAddress((void**)&ql, g_ql);
    cudaGetSymbolAddress((void**)&kh, g_kh);
    cudaGetSymbolAddress((void**)&kl, g_kl);
    cudaGetSymbolAddress((void**)&vh, g_vh);
    cudaGetSymbolAddress((void**)&vl, g_vl);

    static int attr_set = -1;
    size_t gemm_smem = 2 * STAGEB;
    if (attr_set < 0) {
        cudaFuncSetAttribute(attn_kernel, cudaFuncAttributeMaxDynamicSharedMemorySize, ATTN_SMEM);
        cudaFuncSetAttribute(mma_gemm<0>, cudaFuncAttributeMaxDynamicSharedMemorySize, (int)gemm_smem);
        cudaFuncSetAttribute(mma_gemm<1>, cudaFuncAttributeMaxDynamicSharedMemorySize, (int)gemm_smem);
        attr_set = 1;
    }

    /* fused split: X + 4 weights */
    split_multi<<<dim3(512, 5), 256>>>((const float4*)X,
                                       (const float4*)W[0], (const float4*)W[1],
                                       (const float4*)W[2], (const float4*)W[3],
                                       (__nv_bfloat162*)xh, (__nv_bfloat162*)xl,
                                       (__nv_bfloat162*)wh, (__nv_bfloat162*)wl);

    /* fused QKV GEMM: N = 3072 (Wq|Wk|Wv contiguous in g_wh/g_wl) */
    mma_gemm<0><<<dim3(24, 32), 256, gemm_smem>>>(xh, xl, wh, wl, nullptr,
                                                  qh, ql, kh, kl, vh, vl);

    int write_attn = ((size_t)out_size >= (size_t)OUT_ELEMS + ATTN_ELEMS) ? 1 : 0;
    float* attn_out = write_attn ? (out + OUT_ELEMS) : out;
    dim3 agrid(SS / 32, BB * NH);
    attn_kernel<<<agrid, 256, ATTN_SMEM>>>(attn_out, write_attn);

    /* out-projection (attn wrote ctx hi/lo into g_xh/g_xl) */
    mma_gemm<1><<<dim3(8, 32), 256, gemm_smem>>>(xh, xl,
                                                 wh + (size_t)3 * HID * HID,
                                                 wl + (size_t)3 * HID * HID,
                                                 out, nullptr, nullptr, nullptr, nullptr, nullptr, nullptr);
}

// round 9
// speedup vs baseline: 3.8773x; 1.0790x over previous
#include <cuda_runtime.h>
#include <cuda_bf16.h>
#include <cstdint>
#include <math.h>

#define BB 2
#define SS 2048
#define NH 16
#define DH 64
#define HID 1024
#define HALF 256
#define SCALE 0.125f
#define MTOT 4096

#define OUT_ELEMS  (BB*SS*HID)
#define ATTN_ELEMS ((size_t)BB*NH*SS*SS)

/* ---------------- scratch ---------------- */
__device__ __nv_bfloat16 g_xh[MTOT*HID];
__device__ __nv_bfloat16 g_xl[MTOT*HID];
__device__ __nv_bfloat16 g_wh[4][HID*HID];
__device__ __nv_bfloat16 g_wl[4][HID*HID];
__device__ __nv_bfloat16 g_qh[BB*NH*SS*DH];
__device__ __nv_bfloat16 g_ql[BB*NH*SS*DH];
__device__ __nv_bfloat16 g_kh[BB*NH*SS*DH];
__device__ __nv_bfloat16 g_kl[BB*NH*SS*DH];
__device__ __nv_bfloat16 g_vh[BB*NH*SS*DH];
__device__ __nv_bfloat16 g_vl[BB*NH*SS*DH];

/* ---------------- helpers ---------------- */
__device__ __forceinline__ uint32_t smem_u32(const void* p) {
    uint32_t a;
    asm("{ .reg .u64 t; cvta.to.shared.u64 t, %1; cvt.u32.u64 %0, t; }" : "=r"(a) : "l"(p));
    return a;
}
#define CP_ASYNC16(dst, src) asm volatile("cp.async.cg.shared.global [%0], [%1], 16;" :: "r"(dst), "l"(src))
#define CP_COMMIT()          asm volatile("cp.async.commit_group;" ::: "memory")
#define CP_WAIT1()           asm volatile("cp.async.wait_group 1;" ::: "memory")
#define CP_WAIT0()           asm volatile("cp.async.wait_group 0;" ::: "memory")

#define LDMX4(r0,r1,r2,r3,addr) \
    asm volatile("ldmatrix.sync.aligned.m8n8.x4.shared.b16 {%0,%1,%2,%3}, [%4];" \
        : "=r"(r0), "=r"(r1), "=r"(r2), "=r"(r3) : "r"(addr))
#define LDMX4T(r0,r1,r2,r3,addr) \
    asm volatile("ldmatrix.sync.aligned.m8n8.x4.trans.shared.b16 {%0,%1,%2,%3}, [%4];" \
        : "=r"(r0), "=r"(r1), "=r"(r2), "=r"(r3) : "r"(addr))

#define MMA16816(c, a, b) \
    asm volatile("mma.sync.aligned.m16n8k16.row.col.f32.bf16.bf16.f32 " \
        "{%0,%1,%2,%3}, {%4,%5,%6,%7}, {%8,%9}, {%0,%1,%2,%3};" \
        : "+f"((c)[0]), "+f"((c)[1]), "+f"((c)[2]), "+f"((c)[3]) \
        : "r"((a)[0]), "r"((a)[1]), "r"((a)[2]), "r"((a)[3]), "r"((b)[0]), "r"((b)[1]))

__device__ __forceinline__ void split2(float x, float y, __nv_bfloat162& hi, __nv_bfloat162& lo) {
    __nv_bfloat16 h0 = __float2bfloat16(x), h1 = __float2bfloat16(y);
    lo = __nv_bfloat162(__float2bfloat16(x - __bfloat162float(h0)),
                        __float2bfloat16(y - __bfloat162float(h1)));
    hi = __nv_bfloat162(h0, h1);
}

/* ---------------- fused fp32 -> bf16 hi/lo split ---------------- */
__global__ void split_multi(const float4* __restrict__ X,
                            const float4* __restrict__ W0, const float4* __restrict__ W1,
                            const float4* __restrict__ W2, const float4* __restrict__ W3,
                            __nv_bfloat162* __restrict__ xh, __nv_bfloat162* __restrict__ xl,
                            __nv_bfloat162* __restrict__ wh, __nv_bfloat162* __restrict__ wl)
{
    int r = blockIdx.y;
    const float4* src;
    __nv_bfloat162 *hi, *lo;
    int n4;
    if (r == 0) { src = X; hi = xh; lo = xl; n4 = MTOT * HID / 4; }
    else {
        src = (r == 1) ? W0 : (r == 2) ? W1 : (r == 3) ? W2 : W3;
        hi = wh + (size_t)(r - 1) * (HID * HID / 2);
        lo = wl + (size_t)(r - 1) * (HID * HID / 2);
        n4 = HID * HID / 4;
    }
    for (int i = blockIdx.x * blockDim.x + threadIdx.x; i < n4; i += gridDim.x * blockDim.x) {
        float4 x = src[i];
        __nv_bfloat162 h0, l0, h1, l1;
        split2(x.x, x.y, h0, l0);
        split2(x.z, x.w, h1, l1);
        hi[2*i] = h0; hi[2*i+1] = h1;
        lo[2*i] = l0; lo[2*i+1] = l1;
    }
}

/* ---------------- mma.sync split GEMM, SW128-swizzled smem, 3-stage ----------------
 * Tiles: 128 rows x 32 bf16 (64B data) packed 2 rows per 128B line, SW128 XOR.
 * Stage = 4 tiles x 8192 = 32768 B; 3 stages = 98304 B -> 2 CTAs/SM.
 * One __syncthreads per K-iteration.
 */
extern __shared__ char dyn_smem[];

#define GT_TILE  8192
#define GT_STAGE 32768

__device__ __forceinline__ uint32_t sw_phys(uint32_t r, uint32_t colb) {
    uint32_t rowlin = ((r >> 1) << 7) + ((r & 1) << 6);
    return (rowlin + colb) ^ ((rowlin >> 3) & 0x70);
}

template<int MODE>
__global__ __launch_bounds__(256, 2)
void mma_gemm(const __nv_bfloat16* __restrict__ Ah, const __nv_bfloat16* __restrict__ Al,
              const __nv_bfloat16* __restrict__ Bh, const __nv_bfloat16* __restrict__ Bl,
              float* __restrict__ Y,
              __nv_bfloat16* __restrict__ qh, __nv_bfloat16* __restrict__ ql,
              __nv_bfloat16* __restrict__ kh, __nv_bfloat16* __restrict__ kl,
              __nv_bfloat16* __restrict__ vh, __nv_bfloat16* __restrict__ vl)
{
    uint32_t sb = smem_u32(dyn_smem);
    int tid = threadIdx.x, warp = tid >> 5, lane = tid & 31;
    int warpM = warp >> 2, warpN = warp & 3;
    int bm = blockIdx.y * 128, bn = blockIdx.x * 128;

    float acc[4][4][4];
#pragma unroll
    for (int i = 0; i < 4; i++)
#pragma unroll
        for (int j = 0; j < 4; j++)
#pragma unroll
            for (int t = 0; t < 4; t++) acc[i][j][t] = 0.f;

    const __nv_bfloat16* srcs[4] = {Ah, Al, Bh, Bl};

    auto issue_stage = [&](int s, int k0) {
        uint32_t base = sb + s * GT_STAGE;
#pragma unroll
        for (int v = 0; v < 8; v++) {
            int idx = tid + v * 256;
            int t = idx >> 9;
            uint32_t r = (idx >> 2) & 127, seg = idx & 3;
            int rbase = (t < 2) ? bm : bn;
            const __nv_bfloat16* src = srcs[t] + (size_t)(rbase + r) * 1024 + k0 + seg * 8;
            uint32_t dst = base + t * GT_TILE + sw_phys(r, seg * 16);
            CP_ASYNC16(dst, src);
        }
        CP_COMMIT();
    };

    /* precompute swizzled fragment offsets (within tile) */
    uint32_t aOff[4][2], bOff[2][2];
#pragma unroll
    for (int mt = 0; mt < 4; mt++) {
        uint32_t R = warpM * 64 + mt * 16 + (lane & 7) + ((lane >> 3) & 1) * 8;
#pragma unroll
        for (int ks = 0; ks < 2; ks++)
            aOff[mt][ks] = sw_phys(R, (lane >> 4) * 16 + ks * 32);
    }
#pragma unroll
    for (int j = 0; j < 2; j++) {
        uint32_t R = warpN * 32 + j * 16 + (lane & 7) + ((lane >> 4) & 1) * 8;
#pragma unroll
        for (int ks = 0; ks < 2; ks++)
            bOff[j][ks] = sw_phys(R, ((lane >> 3) & 1) * 16 + ks * 32);
    }

    issue_stage(0, 0);
    issue_stage(1, 32);

    int stg = 0;
    for (int it = 0; it < 32; it++) {
        if (it == 31) CP_WAIT0(); else CP_WAIT1();
        __syncthreads();
        if (it + 2 < 32) {
            int s2 = stg + 2; if (s2 >= 3) s2 -= 3;
            issue_stage(s2, (it + 2) * 32);
        }
        uint32_t st = sb + stg * GT_STAGE;

#pragma unroll
        for (int ks = 0; ks < 2; ks++) {
            uint32_t aH[4][4], aL[4][4], bb[4][2];
#pragma unroll
            for (int mt = 0; mt < 4; mt++)
                LDMX4(aH[mt][0], aH[mt][1], aH[mt][2], aH[mt][3], st + aOff[mt][ks]);
            LDMX4(bb[0][0], bb[0][1], bb[1][0], bb[1][1], st + 2 * GT_TILE + bOff[0][ks]);
            LDMX4(bb[2][0], bb[2][1], bb[3][0], bb[3][1], st + 2 * GT_TILE + bOff[1][ks]);
#pragma unroll
            for (int mt = 0; mt < 4; mt++)
#pragma unroll
                for (int nt = 0; nt < 4; nt++)
                    MMA16816(acc[mt][nt], aH[mt], bb[nt]);
#pragma unroll
            for (int mt = 0; mt < 4; mt++)
                LDMX4(aL[mt][0], aL[mt][1], aL[mt][2], aL[mt][3], st + GT_TILE + aOff[mt][ks]);
#pragma unroll
            for (int mt = 0; mt < 4; mt++)
#pragma unroll
                for (int nt = 0; nt < 4; nt++)
                    MMA16816(acc[mt][nt], aL[mt], bb[nt]);
            LDMX4(bb[0][0], bb[0][1], bb[1][0], bb[1][1], st + 3 * GT_TILE + bOff[0][ks]);
            LDMX4(bb[2][0], bb[2][1], bb[3][0], bb[3][1], st + 3 * GT_TILE + bOff[1][ks]);
#pragma unroll
            for (int mt = 0; mt < 4; mt++)
#pragma unroll
                for (int nt = 0; nt < 4; nt++)
                    MMA16816(acc[mt][nt], aH[mt], bb[nt]);
        }
        if (++stg == 3) stg = 0;
    }

    int row0 = lane >> 2, col0 = (lane & 3) * 2;
    __nv_bfloat16 *Yh = nullptr, *Yl = nullptr;
    int nbase = 0;
    if (MODE == 0) {
        int mat = blockIdx.x >> 3;
        Yh = (mat == 0) ? qh : ((mat == 1) ? kh : vh);
        Yl = (mat == 0) ? ql : ((mat == 1) ? kl : vl);
        nbase = (blockIdx.x & 7) * 128;
    }
#pragma unroll
    for (int mt = 0; mt < 4; mt++) {
#pragma unroll
        for (int half = 0; half < 2; half++) {
            int m = bm + warpM * 64 + mt * 16 + row0 + half * 8;
            int b = m >> 11, s = m & 2047;
#pragma unroll
            for (int nt = 0; nt < 4; nt++) {
                float x0 = acc[mt][nt][half * 2 + 0];
                float x1 = acc[mt][nt][half * 2 + 1];
                if (MODE == 0) {
                    int n = nbase + warpN * 32 + nt * 8 + col0;
                    int h = n >> 6, d0 = n & 63;
                    size_t idx = (((size_t)b * NH + h) * SS + s) * DH + d0;
                    __nv_bfloat162 hi, lo;
                    split2(x0, x1, hi, lo);
                    *(__nv_bfloat162*)(Yh + idx) = hi;
                    *(__nv_bfloat162*)(Yl + idx) = lo;
                } else {
                    int n = bn + warpN * 32 + nt * 8 + col0;
                    float2 v2; v2.x = x0; v2.y = x1;
                    *(float2*)(Y + (size_t)m * HID + n) = v2;
                }
            }
        }
    }
}

/* ---------------- tensor-core sliding-window attention ----------------
 * 32 query rows/block, 256 threads (8 warps), window 544 cols.
 * smem: Sh @0 (35328), Sl @35328, Qh @70656 (4608), Ql @75264 (4608),
 *       KV triple-buffer @79872 (3 x 9216) -> total 107520.
 */
#define WW 544
#define SSTR 552
#define OSH 0u
#define OSL 35328u
#define OQH 70656u
#define OQL 75264u
#define OKV 79872u
#define ATTN_SMEM 107520

__global__ __launch_bounds__(256, 2)
void attn_kernel(float* __restrict__ attn_out, int write_attn)
{
    char* sm = dyn_smem;
    uint32_t sb = smem_u32(sm);
    int tid = threadIdx.x, warp = tid >> 5, lane = tid & 31;
    int bh = blockIdx.y;
    int i0 = blockIdx.x * 32;
    int b = bh >> 4, h = bh & 15;
    size_t base = (size_t)bh * SS * DH;
    const __nv_bfloat16 *Qh = g_qh + base, *Ql = g_ql + base;
    const __nv_bfloat16 *Kh = g_kh + base, *Kl = g_kl + base;
    const __nv_bfloat16 *Vh = g_vh + base, *Vl = g_vl + base;
    int jlo = i0 - HALF;

    /* load Q hi/lo tile: 32x64 */
    {
        int row = tid >> 3, seg = tid & 7;
        uint4 vh4 = *(const uint4*)(Qh + (size_t)(i0 + row) * DH + seg * 8);
        uint4 vl4 = *(const uint4*)(Ql + (size_t)(i0 + row) * DH + seg * 8);
        *(uint4*)(sm + OQH + row * 144 + seg * 16) = vh4;
        *(uint4*)(sm + OQL + row * 144 + seg * 16) = vl4;
    }

    auto load_chunk = [&](const __nv_bfloat16* Mh, const __nv_bfloat16* Ml, int c, int buf) {
#pragma unroll
        for (int u = 0; u < 2; u++) {
            int idx = tid + u * 256;
            int hl = idx >> 8, r = (idx >> 3) & 31, seg = idx & 7;
            int j = jlo + c * 32 + r;
            j = (j < 0) ? 0 : ((j > SS - 1) ? SS - 1 : j);
            const __nv_bfloat16* src = (hl ? Ml : Mh) + (size_t)j * DH + seg * 8;
            uint32_t dst = sb + OKV + buf * 9216 + hl * 4608 + r * 144 + seg * 16;
            CP_ASYNC16(dst, src);
        }
        CP_COMMIT();
    };

    /* ---------- phase 1: scores ---------- */
    {
        int mt = warp >> 2, nt = warp & 3;
        uint32_t aoffQ = (uint32_t)((mt * 16 + (lane & 15)) * 144 + (lane >> 4) * 16);
        uint32_t boffK4 = (uint32_t)((nt * 8 + (lane & 7)) * 144 + ((lane >> 3) & 3) * 16);

        load_chunk(Kh, Kl, 0, 0);
        load_chunk(Kh, Kl, 1, 1);
        __syncthreads();            /* Q visible to all */

        uint32_t qHf[4][4], qLf[4][4];
#pragma unroll
        for (int ks = 0; ks < 4; ks++) {
            LDMX4(qHf[ks][0], qHf[ks][1], qHf[ks][2], qHf[ks][3], sb + OQH + aoffQ + ks * 32);
            LDMX4(qLf[ks][0], qLf[ks][1], qLf[ks][2], qLf[ks][3], sb + OQL + aoffQ + ks * 32);
        }

        for (int c = 0; c < 17; c++) {
            if (c == 16) CP_WAIT0(); else CP_WAIT1();
            __syncthreads();
            if (c + 2 < 17) load_chunk(Kh, Kl, c + 2, (c + 2) % 3);
            uint32_t kb = sb + OKV + (c % 3) * 9216;
            float acc[4] = {0.f, 0.f, 0.f, 0.f};
            uint32_t bHf[4][2], bLf[4][2];
            LDMX4(bHf[0][0], bHf[0][1], bHf[1][0], bHf[1][1], kb + boffK4);
            LDMX4(bHf[2][0], bHf[2][1], bHf[3][0], bHf[3][1], kb + boffK4 + 64);
            LDMX4(bLf[0][0], bLf[0][1], bLf[1][0], bLf[1][1], kb + 4608 + boffK4);
            LDMX4(bLf[2][0], bLf[2][1], bLf[3][0], bLf[3][1], kb + 4608 + boffK4 + 64);
#pragma unroll
            for (int ks = 0; ks < 4; ks++) {
                MMA16816(acc, qHf[ks], bHf[ks]);
                MMA16816(acc, qLf[ks], bHf[ks]);
                MMA16816(acc, qHf[ks], bLf[ks]);
            }
            int colb = c * 32 + nt * 8 + (lane & 3) * 2;
#pragma unroll
            for (int half = 0; half < 2; half++) {
                int r = mt * 16 + (lane >> 2) + half * 8;
                int i = i0 + r;
                int j0 = jlo + colb, j1 = j0 + 1;
                float s0 = acc[half * 2 + 0] * SCALE;
                float s1 = acc[half * 2 + 1] * SCALE;
                if (!((j0 >= 0) && (j0 < SS) && (j0 >= i - HALF) && (j0 <= i + HALF))) s0 = -1e30f;
                if (!((j1 >= 0) && (j1 < SS) && (j1 >= i - HALF) && (j1 <= i + HALF))) s1 = -1e30f;
                __nv_bfloat162 hi, lo;
                split2(s0, s1, hi, lo);
                *(__nv_bfloat162*)(sm + OSH + (r * SSTR + colb) * 2) = hi;
                *(__nv_bfloat162*)(sm + OSL + (r * SSTR + colb) * 2) = lo;
            }
        }
        __syncthreads();
    }

    /* prefetch first two V chunks so softmax hides the load latency */
    load_chunk(Vh, Vl, 0, 0);
    load_chunk(Vh, Vl, 1, 1);

    /* ---------- phase 2: softmax ---------- */
    {
        for (int rr = 0; rr < 4; rr++) {
            int r = warp * 4 + rr;
            uint32_t rh = OSH + r * SSTR * 2, rl = OSL + r * SSTR * 2;
            float mx = -1e30f;
            for (int pc = lane; pc < 272; pc += 32) {
                __nv_bfloat162 hh = *(__nv_bfloat162*)(sm + rh + pc * 4);
                __nv_bfloat162 ll = *(__nv_bfloat162*)(sm + rl + pc * 4);
                float s0 = __bfloat162float(hh.x) + __bfloat162float(ll.x);
                float s1 = __bfloat162float(hh.y) + __bfloat162float(ll.y);
                mx = fmaxf(mx, fmaxf(s0, s1));
            }
#pragma unroll
            for (int o = 16; o > 0; o >>= 1) mx = fmaxf(mx, __shfl_xor_sync(0xffffffffu, mx, o));
            float sum = 0.f;
            for (int pc = lane; pc < 272; pc += 32) {
                __nv_bfloat162 hh = *(__nv_bfloat162*)(sm + rh + pc * 4);
                __nv_bfloat162 ll = *(__nv_bfloat162*)(sm + rl + pc * 4);
                float s0 = __bfloat162float(hh.x) + __bfloat162float(ll.x);
                float s1 = __bfloat162float(hh.y) + __bfloat162float(ll.y);
                sum += __expf(s0 - mx) + __expf(s1 - mx);
            }
#pragma unroll
            for (int o = 16; o > 0; o >>= 1) sum += __shfl_xor_sync(0xffffffffu, sum, o);
            float inv = 1.f / sum;
            for (int pc = lane; pc < 272; pc += 32) {
                __nv_bfloat162 hh = *(__nv_bfloat162*)(sm + rh + pc * 4);
                __nv_bfloat162 ll = *(__nv_bfloat162*)(sm + rl + pc * 4);
                float s0 = __bfloat162float(hh.x) + __bfloat162float(ll.x);
                float s1 = __bfloat162float(hh.y) + __bfloat162float(ll.y);
                float p0 = __expf(s0 - mx) * inv;
                float p1 = __expf(s1 - mx) * inv;
                __nv_bfloat162 hi, lo;
                split2(p0, p1, hi, lo);
                *(__nv_bfloat162*)(sm + rh + pc * 4) = hi;
                *(__nv_bfloat162*)(sm + rl + pc * 4) = lo;
            }
        }
        __syncthreads();
    }

    /* ---------- phase 2.5: write attn tensor ---------- */
    if (write_attn) {
        for (int rr = 0; rr < 4; rr++) {
            int r = warp * 4 + rr;
            int i = i0 + r;
            float* row = attn_out + ((size_t)bh * SS + i) * SS;
            uint32_t rh = OSH + r * SSTR * 2, rl = OSL + r * SSTR * 2;
            for (int j4 = lane * 4; j4 < SS; j4 += 128) {
                float4 v4;
                float* vv = (float*)&v4;
#pragma unroll
                for (int e = 0; e < 4; e++) {
                    int cidx = j4 + e - jlo;
                    float p = 0.f;
                    if (cidx >= 0 && cidx < WW) {
                        __nv_bfloat16 ph = *(__nv_bfloat16*)(sm + rh + cidx * 2);
                        __nv_bfloat16 pl = *(__nv_bfloat16*)(sm + rl + cidx * 2);
                        p = __bfloat162float(ph) + __bfloat162float(pl);
                    }
                    vv[e] = p;
                }
                *(float4*)(row + j4) = v4;
            }
        }
    }

    /* ---------- phase 3: PV ---------- */
    {
        int mtp = warp >> 2;
        int ntb = (warp & 3) * 2;
        float oacc[2][4];
#pragma unroll
        for (int p = 0; p < 2; p++)
#pragma unroll
            for (int t = 0; t < 4; t++) oacc[p][t] = 0.f;

        uint32_t aoffP = (uint32_t)((mtp * 16 + (lane & 15)) * SSTR * 2 + (lane >> 4) * 16);
        uint32_t vrow4 = (uint32_t)((((lane & 7) + ((lane >> 3) & 1) * 8)) * 144 + (lane >> 4) * 16);

        for (int c = 0; c < 17; c++) {
            if (c == 16) CP_WAIT0(); else CP_WAIT1();
            __syncthreads();
            if (c + 2 < 17) load_chunk(Vh, Vl, c + 2, (c + 2) % 3);
            uint32_t vb = sb + OKV + (c % 3) * 9216;
#pragma unroll
            for (int ks = 0; ks < 2; ks++) {
                uint32_t aH[4], aL[4];
                LDMX4(aH[0], aH[1], aH[2], aH[3], sb + OSH + aoffP + (c * 32 + ks * 16) * 2);
                LDMX4(aL[0], aL[1], aL[2], aL[3], sb + OSL + aoffP + (c * 32 + ks * 16) * 2);
                uint32_t bHf[2][2], bLf[2][2];
                uint32_t va = vb + vrow4 + ks * 16 * 144 + ntb * 16;
                LDMX4T(bHf[0][0], bHf[0][1], bHf[1][0], bHf[1][1], va);
                LDMX4T(bLf[0][0], bLf[0][1], bLf[1][0], bLf[1][1], va + 4608);
#pragma unroll
                for (int p = 0; p < 2; p++) {
                    MMA16816(oacc[p], aH, bHf[p]);
                    MMA16816(oacc[p], aL, bHf[p]);
                    MMA16816(oacc[p], aH, bLf[p]);
                }
            }
        }

        /* write ctx as bf16 hi/lo into g_xh/g_xl */
        int row0 = lane >> 2, col0 = (lane & 3) * 2;
#pragma unroll
        for (int p = 0; p < 2; p++) {
            int nt = ntb + p;
#pragma unroll
            for (int half = 0; half < 2; half++) {
                int i = i0 + mtp * 16 + row0 + half * 8;
                size_t m = (size_t)b * SS + i;
                int d = nt * 8 + col0;
                float x0 = oacc[p][half * 2 + 0];
                float x1 = oacc[p][half * 2 + 1];
                __nv_bfloat162 hi, lo;
                split2(x0, x1, hi, lo);
                size_t idx = m * HID + h * DH + d;
                *(__nv_bfloat162*)(g_xh + idx) = hi;
                *(__nv_bfloat162*)(g_xl + idx) = lo;
            }
        }
    }
}

/* ---------------- launch ---------------- */
extern "C" void kernel_launch(void* const* d_in, const int* in_sizes, int n_in,
                              void* d_out, int out_size)
{
    const float* X = (const float*)d_in[0];
    const float* W[4] = {(const float*)d_in[1], (const float*)d_in[2],
                         (const float*)d_in[3], (const float*)d_in[4]};
    float* out = (float*)d_out;

    __nv_bfloat16 *xh, *xl, *wh, *wl, *qh, *ql, *kh, *kl, *vh, *vl;
    cudaGetSymbolAddress((void**)&xh, g_xh);
    cudaGetSymbolAddress((void**)&xl, g_xl);
    cudaGetSymbolAddress((void**)&wh, g_wh);
    cudaGetSymbolAddress((void**)&wl, g_wl);
    cudaGetSymbolAddress((void**)&qh, g_qh);
    cudaGetSymbolAddress((void**)&ql, g_ql);
    cudaGetSymbolAddress((void**)&kh, g_kh);
    cudaGetSymbolAddress((void**)&kl, g_kl);
    cudaGetSymbolAddress((void**)&vh, g_vh);
    cudaGetSymbolAddress((void**)&vl, g_vl);

    static int attr_set = -1;
    size_t gemm_smem = 3 * GT_STAGE;   /* 98304 */
    if (attr_set < 0) {
        cudaFuncSetAttribute(attn_kernel, cudaFuncAttributeMaxDynamicSharedMemorySize, ATTN_SMEM);
        cudaFuncSetAttribute(mma_gemm<0>, cudaFuncAttributeMaxDynamicSharedMemorySize, (int)gemm_smem);
        cudaFuncSetAttribute(mma_gemm<1>, cudaFuncAttributeMaxDynamicSharedMemorySize, (int)gemm_smem);
        attr_set = 1;
    }

    split_multi<<<dim3(512, 5), 256>>>((const float4*)X,
                                       (const float4*)W[0], (const float4*)W[1],
                                       (const float4*)W[2], (const float4*)W[3],
                                       (__nv_bfloat162*)xh, (__nv_bfloat162*)xl,
                                       (__nv_bfloat162*)wh, (__nv_bfloat162*)wl);

    /* fused QKV GEMM: N = 3072 */
    mma_gemm<0><<<dim3(24, 32), 256, gemm_smem>>>(xh, xl, wh, wl, nullptr,
                                                  qh, ql, kh, kl, vh, vl);

    int write_attn = ((size_t)out_size >= (size_t)OUT_ELEMS + ATTN_ELEMS) ? 1 : 0;
    float* attn_out = write_attn ? (out + OUT_ELEMS) : out;
    dim3 agrid(SS / 32, BB * NH);
    attn_kernel<<<agrid, 256, ATTN_SMEM>>>(attn_out, write_attn);

    mma_gemm<1><<<dim3(8, 32), 256, gemm_smem>>>(xh, xl,
                                                 wh + (size_t)3 * HID * HID,
                                                 wl + (size_t)3 * HID * HID,
                                                 out, nullptr, nullptr, nullptr, nullptr, nullptr, nullptr);
}

// round 10
// speedup vs baseline: 4.0304x; 1.0395x over previous
#include <cuda_runtime.h>
#include <cuda_bf16.h>
#include <cstdint>
#include <math.h>

#define BB 2
#define SS 2048
#define NH 16
#define DH 64
#define HID 1024
#define HALF 256
#define SCALE 0.125f
#define MTOT 4096

#define OUT_ELEMS  (BB*SS*HID)
#define ATTN_ELEMS ((size_t)BB*NH*SS*SS)

/* ---------------- scratch ---------------- */
__device__ __nv_bfloat16 g_xh[MTOT*HID];
__device__ __nv_bfloat16 g_xl[MTOT*HID];
__device__ __nv_bfloat16 g_wh[4][HID*HID];
__device__ __nv_bfloat16 g_wl[4][HID*HID];
__device__ __nv_bfloat16 g_qh[BB*NH*SS*DH];
__device__ __nv_bfloat16 g_ql[BB*NH*SS*DH];
__device__ __nv_bfloat16 g_kh[BB*NH*SS*DH];
__device__ __nv_bfloat16 g_kl[BB*NH*SS*DH];
__device__ __nv_bfloat16 g_vh[BB*NH*SS*DH];
__device__ __nv_bfloat16 g_vl[BB*NH*SS*DH];

/* ---------------- helpers ---------------- */
__device__ __forceinline__ uint32_t smem_u32(const void* p) {
    uint32_t a;
    asm("{ .reg .u64 t; cvta.to.shared.u64 t, %1; cvt.u32.u64 %0, t; }" : "=r"(a) : "l"(p));
    return a;
}
#define CP_ASYNC16(dst, src) asm volatile("cp.async.cg.shared.global [%0], [%1], 16;" :: "r"(dst), "l"(src))
#define CP_COMMIT()          asm volatile("cp.async.commit_group;" ::: "memory")
#define CP_WAIT1()           asm volatile("cp.async.wait_group 1;" ::: "memory")
#define CP_WAIT0()           asm volatile("cp.async.wait_group 0;" ::: "memory")

#define LDMX4(r0,r1,r2,r3,addr) \
    asm volatile("ldmatrix.sync.aligned.m8n8.x4.shared.b16 {%0,%1,%2,%3}, [%4];" \
        : "=r"(r0), "=r"(r1), "=r"(r2), "=r"(r3) : "r"(addr))
#define LDMX4T(r0,r1,r2,r3,addr) \
    asm volatile("ldmatrix.sync.aligned.m8n8.x4.trans.shared.b16 {%0,%1,%2,%3}, [%4];" \
        : "=r"(r0), "=r"(r1), "=r"(r2), "=r"(r3) : "r"(addr))

#define MMA16816(c, a, b) \
    asm volatile("mma.sync.aligned.m16n8k16.row.col.f32.bf16.bf16.f32 " \
        "{%0,%1,%2,%3}, {%4,%5,%6,%7}, {%8,%9}, {%0,%1,%2,%3};" \
        : "+f"((c)[0]), "+f"((c)[1]), "+f"((c)[2]), "+f"((c)[3]) \
        : "r"((a)[0]), "r"((a)[1]), "r"((a)[2]), "r"((a)[3]), "r"((b)[0]), "r"((b)[1]))

__device__ __forceinline__ void split2(float x, float y, __nv_bfloat162& hi, __nv_bfloat162& lo) {
    __nv_bfloat16 h0 = __float2bfloat16(x), h1 = __float2bfloat16(y);
    lo = __nv_bfloat162(__float2bfloat16(x - __bfloat162float(h0)),
                        __float2bfloat16(y - __bfloat162float(h1)));
    hi = __nv_bfloat162(h0, h1);
}

/* ---------------- fused fp32 -> bf16 hi/lo split ---------------- */
__global__ void split_multi(const float4* __restrict__ X,
                            const float4* __restrict__ W0, const float4* __restrict__ W1,
                            const float4* __restrict__ W2, const float4* __restrict__ W3,
                            __nv_bfloat162* __restrict__ xh, __nv_bfloat162* __restrict__ xl,
                            __nv_bfloat162* __restrict__ wh, __nv_bfloat162* __restrict__ wl)
{
    int r = blockIdx.y;
    const float4* src;
    __nv_bfloat162 *hi, *lo;
    int n4;
    if (r == 0) { src = X; hi = xh; lo = xl; n4 = MTOT * HID / 4; }
    else {
        src = (r == 1) ? W0 : (r == 2) ? W1 : (r == 3) ? W2 : W3;
        hi = wh + (size_t)(r - 1) * (HID * HID / 2);
        lo = wl + (size_t)(r - 1) * (HID * HID / 2);
        n4 = HID * HID / 4;
    }
    for (int i = blockIdx.x * blockDim.x + threadIdx.x; i < n4; i += gridDim.x * blockDim.x) {
        float4 x = src[i];
        __nv_bfloat162 h0, l0, h1, l1;
        split2(x.x, x.y, h0, l0);
        split2(x.z, x.w, h1, l1);
        hi[2*i] = h0; hi[2*i+1] = h1;
        lo[2*i] = l0; lo[2*i+1] = l1;
    }
}

/* ---------------- mma.sync split GEMM, SW128-swizzled smem, 3-stage ---------------- */
extern __shared__ char dyn_smem[];

#define GT_TILE  8192
#define GT_STAGE 32768

__device__ __forceinline__ uint32_t sw_phys(uint32_t r, uint32_t colb) {
    uint32_t rowlin = ((r >> 1) << 7) + ((r & 1) << 6);
    return (rowlin + colb) ^ ((rowlin >> 3) & 0x70);
}

template<int MODE>
__global__ __launch_bounds__(256, 2)
void mma_gemm(const __nv_bfloat16* __restrict__ Ah, const __nv_bfloat16* __restrict__ Al,
              const __nv_bfloat16* __restrict__ Bh, const __nv_bfloat16* __restrict__ Bl,
              float* __restrict__ Y,
              __nv_bfloat16* __restrict__ qh, __nv_bfloat16* __restrict__ ql,
              __nv_bfloat16* __restrict__ kh, __nv_bfloat16* __restrict__ kl,
              __nv_bfloat16* __restrict__ vh, __nv_bfloat16* __restrict__ vl)
{
    uint32_t sb = smem_u32(dyn_smem);
    int tid = threadIdx.x, warp = tid >> 5, lane = tid & 31;
    int warpM = warp >> 2, warpN = warp & 3;
    int bm = blockIdx.y * 128, bn = blockIdx.x * 128;

    float acc[4][4][4];
#pragma unroll
    for (int i = 0; i < 4; i++)
#pragma unroll
        for (int j = 0; j < 4; j++)
#pragma unroll
            for (int t = 0; t < 4; t++) acc[i][j][t] = 0.f;

    const __nv_bfloat16* srcs[4] = {Ah, Al, Bh, Bl};

    auto issue_stage = [&](int s, int k0) {
        uint32_t base = sb + s * GT_STAGE;
#pragma unroll
        for (int v = 0; v < 8; v++) {
            int idx = tid + v * 256;
            int t = idx >> 9;
            uint32_t r = (idx >> 2) & 127, seg = idx & 3;
            int rbase = (t < 2) ? bm : bn;
            const __nv_bfloat16* src = srcs[t] + (size_t)(rbase + r) * 1024 + k0 + seg * 8;
            uint32_t dst = base + t * GT_TILE + sw_phys(r, seg * 16);
            CP_ASYNC16(dst, src);
        }
        CP_COMMIT();
    };

    uint32_t aOff[4][2], bOff[2][2];
#pragma unroll
    for (int mt = 0; mt < 4; mt++) {
        uint32_t R = warpM * 64 + mt * 16 + (lane & 7) + ((lane >> 3) & 1) * 8;
#pragma unroll
        for (int ks = 0; ks < 2; ks++)
            aOff[mt][ks] = sw_phys(R, (lane >> 4) * 16 + ks * 32);
    }
#pragma unroll
    for (int j = 0; j < 2; j++) {
        uint32_t R = warpN * 32 + j * 16 + (lane & 7) + ((lane >> 4) & 1) * 8;
#pragma unroll
        for (int ks = 0; ks < 2; ks++)
            bOff[j][ks] = sw_phys(R, ((lane >> 3) & 1) * 16 + ks * 32);
    }

    issue_stage(0, 0);
    issue_stage(1, 32);

    int stg = 0;
    for (int it = 0; it < 32; it++) {
        if (it == 31) CP_WAIT0(); else CP_WAIT1();
        __syncthreads();
        if (it + 2 < 32) {
            int s2 = stg + 2; if (s2 >= 3) s2 -= 3;
            issue_stage(s2, (it + 2) * 32);
        }
        uint32_t st = sb + stg * GT_STAGE;

#pragma unroll
        for (int ks = 0; ks < 2; ks++) {
            uint32_t aH[4][4], aL[4][4], bb[4][2];
#pragma unroll
            for (int mt = 0; mt < 4; mt++)
                LDMX4(aH[mt][0], aH[mt][1], aH[mt][2], aH[mt][3], st + aOff[mt][ks]);
            LDMX4(bb[0][0], bb[0][1], bb[1][0], bb[1][1], st + 2 * GT_TILE + bOff[0][ks]);
            LDMX4(bb[2][0], bb[2][1], bb[3][0], bb[3][1], st + 2 * GT_TILE + bOff[1][ks]);
#pragma unroll
            for (int mt = 0; mt < 4; mt++)
#pragma unroll
                for (int nt = 0; nt < 4; nt++)
                    MMA16816(acc[mt][nt], aH[mt], bb[nt]);
#pragma unroll
            for (int mt = 0; mt < 4; mt++)
                LDMX4(aL[mt][0], aL[mt][1], aL[mt][2], aL[mt][3], st + GT_TILE + aOff[mt][ks]);
#pragma unroll
            for (int mt = 0; mt < 4; mt++)
#pragma unroll
                for (int nt = 0; nt < 4; nt++)
                    MMA16816(acc[mt][nt], aL[mt], bb[nt]);
            LDMX4(bb[0][0], bb[0][1], bb[1][0], bb[1][1], st + 3 * GT_TILE + bOff[0][ks]);
            LDMX4(bb[2][0], bb[2][1], bb[3][0], bb[3][1], st + 3 * GT_TILE + bOff[1][ks]);
#pragma unroll
            for (int mt = 0; mt < 4; mt++)
#pragma unroll
                for (int nt = 0; nt < 4; nt++)
                    MMA16816(acc[mt][nt], aH[mt], bb[nt]);
        }
        if (++stg == 3) stg = 0;
    }

    int row0 = lane >> 2, col0 = (lane & 3) * 2;
    __nv_bfloat16 *Yh = nullptr, *Yl = nullptr;
    int nbase = 0;
    if (MODE == 0) {
        int mat = blockIdx.x >> 3;
        Yh = (mat == 0) ? qh : ((mat == 1) ? kh : vh);
        Yl = (mat == 0) ? ql : ((mat == 1) ? kl : vl);
        nbase = (blockIdx.x & 7) * 128;
    }
#pragma unroll
    for (int mt = 0; mt < 4; mt++) {
#pragma unroll
        for (int half = 0; half < 2; half++) {
            int m = bm + warpM * 64 + mt * 16 + row0 + half * 8;
            int b = m >> 11, s = m & 2047;
#pragma unroll
            for (int nt = 0; nt < 4; nt++) {
                float x0 = acc[mt][nt][half * 2 + 0];
                float x1 = acc[mt][nt][half * 2 + 1];
                if (MODE == 0) {
                    int n = nbase + warpN * 32 + nt * 8 + col0;
                    int h = n >> 6, d0 = n & 63;
                    size_t idx = (((size_t)b * NH + h) * SS + s) * DH + d0;
                    __nv_bfloat162 hi, lo;
                    split2(x0, x1, hi, lo);
                    *(__nv_bfloat162*)(Yh + idx) = hi;
                    *(__nv_bfloat162*)(Yl + idx) = lo;
                } else {
                    int n = bn + warpN * 32 + nt * 8 + col0;
                    float2 v2; v2.x = x0; v2.y = x1;
                    *(float2*)(Y + (size_t)m * HID + n) = v2;
                }
            }
        }
    }
}

/* ---------------- tensor-core sliding-window attention ----------------
 * smem: Sh @0, Sl @35328, Qh @70656, Ql @75264, KV x3 @79872, inv[32] @107520.
 */
#define WW 544
#define SSTR 552
#define OSH 0u
#define OSL 35328u
#define OQH 70656u
#define OQL 75264u
#define OKV 79872u
#define OINV 107520u
#define ATTN_SMEM 107648

__global__ __launch_bounds__(256, 2)
void attn_kernel(float* __restrict__ attn_out, int write_attn)
{
    char* sm = dyn_smem;
    uint32_t sb = smem_u32(sm);
    int tid = threadIdx.x, warp = tid >> 5, lane = tid & 31;
    int bh = blockIdx.y;
    int i0 = blockIdx.x * 32;
    int b = bh >> 4, h = bh & 15;
    size_t base = (size_t)bh * SS * DH;
    const __nv_bfloat16 *Qh = g_qh + base, *Ql = g_ql + base;
    const __nv_bfloat16 *Kh = g_kh + base, *Kl = g_kl + base;
    const __nv_bfloat16 *Vh = g_vh + base, *Vl = g_vl + base;
    int jlo = i0 - HALF;

    /* load Q hi/lo tile: 32x64 */
    {
        int row = tid >> 3, seg = tid & 7;
        uint4 vh4 = *(const uint4*)(Qh + (size_t)(i0 + row) * DH + seg * 8);
        uint4 vl4 = *(const uint4*)(Ql + (size_t)(i0 + row) * DH + seg * 8);
        *(uint4*)(sm + OQH + row * 144 + seg * 16) = vh4;
        *(uint4*)(sm + OQL + row * 144 + seg * 16) = vl4;
    }

    auto load_chunk = [&](const __nv_bfloat16* Mh, const __nv_bfloat16* Ml, int c, int buf) {
#pragma unroll
        for (int u = 0; u < 2; u++) {
            int idx = tid + u * 256;
            int hl = idx >> 8, r = (idx >> 3) & 31, seg = idx & 7;
            int j = jlo + c * 32 + r;
            j = (j < 0) ? 0 : ((j > SS - 1) ? SS - 1 : j);
            const __nv_bfloat16* src = (hl ? Ml : Mh) + (size_t)j * DH + seg * 8;
            uint32_t dst = sb + OKV + buf * 9216 + hl * 4608 + r * 144 + seg * 16;
            CP_ASYNC16(dst, src);
        }
        CP_COMMIT();
    };

    /* ---------- phase 1: scores ---------- */
    {
        int mt = warp >> 2, nt = warp & 3;
        uint32_t aoffQ = (uint32_t)((mt * 16 + (lane & 15)) * 144 + (lane >> 4) * 16);
        uint32_t boffK4 = (uint32_t)((nt * 8 + (lane & 7)) * 144 + ((lane >> 3) & 3) * 16);

        load_chunk(Kh, Kl, 0, 0);
        load_chunk(Kh, Kl, 1, 1);
        __syncthreads();

        uint32_t qHf[4][4], qLf[4][4];
#pragma unroll
        for (int ks = 0; ks < 4; ks++) {
            LDMX4(qHf[ks][0], qHf[ks][1], qHf[ks][2], qHf[ks][3], sb + OQH + aoffQ + ks * 32);
            LDMX4(qLf[ks][0], qLf[ks][1], qLf[ks][2], qLf[ks][3], sb + OQL + aoffQ + ks * 32);
        }

        for (int c = 0; c < 17; c++) {
            if (c == 16) CP_WAIT0(); else CP_WAIT1();
            __syncthreads();
            if (c + 2 < 17) load_chunk(Kh, Kl, c + 2, (c + 2) % 3);
            uint32_t kb = sb + OKV + (c % 3) * 9216;
            float acc[4] = {0.f, 0.f, 0.f, 0.f};
            uint32_t bHf[4][2], bLf[4][2];
            LDMX4(bHf[0][0], bHf[0][1], bHf[1][0], bHf[1][1], kb + boffK4);
            LDMX4(bHf[2][0], bHf[2][1], bHf[3][0], bHf[3][1], kb + boffK4 + 64);
            LDMX4(bLf[0][0], bLf[0][1], bLf[1][0], bLf[1][1], kb + 4608 + boffK4);
            LDMX4(bLf[2][0], bLf[2][1], bLf[3][0], bLf[3][1], kb + 4608 + boffK4 + 64);
#pragma unroll
            for (int ks = 0; ks < 4; ks++) {
                MMA16816(acc, qHf[ks], bHf[ks]);
                MMA16816(acc, qLf[ks], bHf[ks]);
                MMA16816(acc, qHf[ks], bLf[ks]);
            }
            int colb = c * 32 + nt * 8 + (lane & 3) * 2;
#pragma unroll
            for (int half = 0; half < 2; half++) {
                int r = mt * 16 + (lane >> 2) + half * 8;
                int i = i0 + r;
                int j0 = jlo + colb, j1 = j0 + 1;
                float s0 = acc[half * 2 + 0] * SCALE;
                float s1 = acc[half * 2 + 1] * SCALE;
                if (!((j0 >= 0) && (j0 < SS) && (j0 >= i - HALF) && (j0 <= i + HALF))) s0 = -1e30f;
                if (!((j1 >= 0) && (j1 < SS) && (j1 >= i - HALF) && (j1 <= i + HALF))) s1 = -1e30f;
                __nv_bfloat162 hi, lo;
                split2(s0, s1, hi, lo);
                *(__nv_bfloat162*)(sm + OSH + (r * SSTR + colb) * 2) = hi;
                *(__nv_bfloat162*)(sm + OSL + (r * SSTR + colb) * 2) = lo;
            }
        }
        __syncthreads();
    }

    /* prefetch first two V chunks so softmax hides the load latency */
    load_chunk(Vh, Vl, 0, 0);
    load_chunk(Vh, Vl, 1, 1);

    /* ---------- phase 2: softmax, 2-pass, deferred normalization ----------
     * Stores E = exp(s - max) hi/lo in place; inv = 1/sum in smem per row. */
    {
        for (int rr = 0; rr < 4; rr++) {
            int r = warp * 4 + rr;
            uint32_t rh = OSH + r * SSTR * 2, rl = OSL + r * SSTR * 2;
            float mx = -1e30f;
            for (int pc = lane; pc < 272; pc += 32) {
                __nv_bfloat162 hh = *(__nv_bfloat162*)(sm + rh + pc * 4);
                __nv_bfloat162 ll = *(__nv_bfloat162*)(sm + rl + pc * 4);
                float s0 = __bfloat162float(hh.x) + __bfloat162float(ll.x);
                float s1 = __bfloat162float(hh.y) + __bfloat162float(ll.y);
                mx = fmaxf(mx, fmaxf(s0, s1));
            }
#pragma unroll
            for (int o = 16; o > 0; o >>= 1) mx = fmaxf(mx, __shfl_xor_sync(0xffffffffu, mx, o));
            float sum = 0.f;
            for (int pc = lane; pc < 272; pc += 32) {
                __nv_bfloat162 hh = *(__nv_bfloat162*)(sm + rh + pc * 4);
                __nv_bfloat162 ll = *(__nv_bfloat162*)(sm + rl + pc * 4);
                float s0 = __bfloat162float(hh.x) + __bfloat162float(ll.x);
                float s1 = __bfloat162float(hh.y) + __bfloat162float(ll.y);
                float e0 = __expf(s0 - mx);
                float e1 = __expf(s1 - mx);
                sum += e0 + e1;
                __nv_bfloat162 hi, lo;
                split2(e0, e1, hi, lo);
                *(__nv_bfloat162*)(sm + rh + pc * 4) = hi;
                *(__nv_bfloat162*)(sm + rl + pc * 4) = lo;
            }
#pragma unroll
            for (int o = 16; o > 0; o >>= 1) sum += __shfl_xor_sync(0xffffffffu, sum, o);
            if (lane == 0) ((float*)(sm + OINV))[r] = 1.f / sum;
        }
        __syncthreads();
    }

    /* ---------- phase 2.5: write attn tensor (vectorized smem reads) ---------- */
    if (write_attn) {
        for (int rr = 0; rr < 4; rr++) {
            int r = warp * 4 + rr;
            int i = i0 + r;
            float inv = ((float*)(sm + OINV))[r];
            float* row = attn_out + ((size_t)bh * SS + i) * SS;
            uint32_t rh = OSH + r * SSTR * 2, rl = OSL + r * SSTR * 2;
            for (int j4 = lane * 4; j4 < SS; j4 += 128) {
                int cidx = j4 - jlo;   /* multiple of 4; window [0,WW) 4-aligned */
                float4 v4;
                if (cidx >= 0 && cidx < WW) {
                    uint2 uh = *(uint2*)(sm + rh + cidx * 2);
                    uint2 ul = *(uint2*)(sm + rl + cidx * 2);
                    __nv_bfloat162 h0 = *(__nv_bfloat162*)&uh.x;
                    __nv_bfloat162 h1 = *(__nv_bfloat162*)&uh.y;
                    __nv_bfloat162 l0 = *(__nv_bfloat162*)&ul.x;
                    __nv_bfloat162 l1 = *(__nv_bfloat162*)&ul.y;
                    v4.x = (__bfloat162float(h0.x) + __bfloat162float(l0.x)) * inv;
                    v4.y = (__bfloat162float(h0.y) + __bfloat162float(l0.y)) * inv;
                    v4.z = (__bfloat162float(h1.x) + __bfloat162float(l1.x)) * inv;
                    v4.w = (__bfloat162float(h1.y) + __bfloat162float(l1.y)) * inv;
                } else {
                    v4.x = v4.y = v4.z = v4.w = 0.f;
                }
                *(float4*)(row + j4) = v4;
            }
        }
    }

    /* ---------- phase 3: PV (on unnormalized E; scale at epilogue) ---------- */
    {
        int mtp = warp >> 2;
        int ntb = (warp & 3) * 2;
        float oacc[2][4];
#pragma unroll
        for (int p = 0; p < 2; p++)
#pragma unroll
            for (int t = 0; t < 4; t++) oacc[p][t] = 0.f;

        uint32_t aoffP = (uint32_t)((mtp * 16 + (lane & 15)) * SSTR * 2 + (lane >> 4) * 16);
        uint32_t vrow4 = (uint32_t)((((lane & 7) + ((lane >> 3) & 1) * 8)) * 144 + (lane >> 4) * 16);

        for (int c = 0; c < 17; c++) {
            if (c == 16) CP_WAIT0(); else CP_WAIT1();
            __syncthreads();
            if (c + 2 < 17) load_chunk(Vh, Vl, c + 2, (c + 2) % 3);
            uint32_t vb = sb + OKV + (c % 3) * 9216;
#pragma unroll
            for (int ks = 0; ks < 2; ks++) {
                uint32_t aH[4], aL[4];
                LDMX4(aH[0], aH[1], aH[2], aH[3], sb + OSH + aoffP + (c * 32 + ks * 16) * 2);
                LDMX4(aL[0], aL[1], aL[2], aL[3], sb + OSL + aoffP + (c * 32 + ks * 16) * 2);
                uint32_t bHf[2][2], bLf[2][2];
                uint32_t va = vb + vrow4 + ks * 16 * 144 + ntb * 16;
                LDMX4T(bHf[0][0], bHf[0][1], bHf[1][0], bHf[1][1], va);
                LDMX4T(bLf[0][0], bLf[0][1], bLf[1][0], bLf[1][1], va + 4608);
#pragma unroll
                for (int p = 0; p < 2; p++) {
                    MMA16816(oacc[p], aH, bHf[p]);
                    MMA16816(oacc[p], aL, bHf[p]);
                    MMA16816(oacc[p], aH, bLf[p]);
                }
            }
        }

        int row0 = lane >> 2, col0 = (lane & 3) * 2;
        float invA = ((float*)(sm + OINV))[mtp * 16 + row0];
        float invB = ((float*)(sm + OINV))[mtp * 16 + row0 + 8];
#pragma unroll
        for (int p = 0; p < 2; p++) {
            int nt = ntb + p;
#pragma unroll
            for (int half = 0; half < 2; half++) {
                float inv = half ? invB : invA;
                int i = i0 + mtp * 16 + row0 + half * 8;
                size_t m = (size_t)b * SS + i;
                int d = nt * 8 + col0;
                float x0 = oacc[p][half * 2 + 0] * inv;
                float x1 = oacc[p][half * 2 + 1] * inv;
                __nv_bfloat162 hi, lo;
                split2(x0, x1, hi, lo);
                size_t idx = m * HID + h * DH + d;
                *(__nv_bfloat162*)(g_xh + idx) = hi;
                *(__nv_bfloat162*)(g_xl + idx) = lo;
            }
        }
    }
}

/* ---------------- launch ---------------- */
extern "C" void kernel_launch(void* const* d_in, const int* in_sizes, int n_in,
                              void* d_out, int out_size)
{
    const float* X = (const float*)d_in[0];
    const float* W[4] = {(const float*)d_in[1], (const float*)d_in[2],
                         (const float*)d_in[3], (const float*)d_in[4]};
    float* out = (float*)d_out;

    __nv_bfloat16 *xh, *xl, *wh, *wl, *qh, *ql, *kh, *kl, *vh, *vl;
    cudaGetSymbolAddress((void**)&xh, g_xh);
    cudaGetSymbolAddress((void**)&xl, g_xl);
    cudaGetSymbolAddress((void**)&wh, g_wh);
    cudaGetSymbolAddress((void**)&wl, g_wl);
    cudaGetSymbolAddress((void**)&qh, g_qh);
    cudaGetSymbolAddress((void**)&ql, g_ql);
    cudaGetSymbolAddress((void**)&kh, g_kh);
    cudaGetSymbolAddress((void**)&kl, g_kl);
    cudaGetSymbolAddress((void**)&vh, g_vh);
    cudaGetSymbolAddress((void**)&vl, g_vl);

    static int attr_set = -1;
    size_t gemm_smem = 3 * GT_STAGE;
    if (attr_set < 0) {
        cudaFuncSetAttribute(attn_kernel, cudaFuncAttributeMaxDynamicSharedMemorySize, ATTN_SMEM);
        cudaFuncSetAttribute(mma_gemm<0>, cudaFuncAttributeMaxDynamicSharedMemorySize, (int)gemm_smem);
        cudaFuncSetAttribute(mma_gemm<1>, cudaFuncAttributeMaxDynamicSharedMemorySize, (int)gemm_smem);
        attr_set = 1;
    }

    split_multi<<<dim3(512, 5), 256>>>((const float4*)X,
                                       (const float4*)W[0], (const float4*)W[1],
                                       (const float4*)W[2], (const float4*)W[3],
                                       (__nv_bfloat162*)xh, (__nv_bfloat162*)xl,
                                       (__nv_bfloat162*)wh, (__nv_bfloat162*)wl);

    mma_gemm<0><<<dim3(24, 32), 256, gemm_smem>>>(xh, xl, wh, wl, nullptr,
                                                  qh, ql, kh, kl, vh, vl);

    int write_attn = ((size_t)out_size >= (size_t)OUT_ELEMS + ATTN_ELEMS) ? 1 : 0;
    float* attn_out = write_attn ? (out + OUT_ELEMS) : out;
    dim3 agrid(SS / 32, BB * NH);
    attn_kernel<<<agrid, 256, ATTN_SMEM>>>(attn_out, write_attn);

    mma_gemm<1><<<dim3(8, 32), 256, gemm_smem>>>(xh, xl,
                                                 wh + (size_t)3 * HID * HID,
                                                 wl + (size_t)3 * HID * HID,
                                                 out, nullptr, nullptr, nullptr, nullptr, nullptr, nullptr);
}

// round 11
// speedup vs baseline: 4.0573x; 1.0067x over previous
#include <cuda_runtime.h>
#include <cuda_bf16.h>
#include <cstdint>
#include <math.h>

#define BB 2
#define SS 2048
#define NH 16
#define DH 64
#define HID 1024
#define HALF 256
#define SCALE 0.125f
#define MTOT 4096

#define OUT_ELEMS  (BB*SS*HID)
#define ATTN_ELEMS ((size_t)BB*NH*SS*SS)
#define ATTN_F4    (ATTN_ELEMS/4)   /* 33554432 */

/* ---------------- scratch ---------------- */
__device__ __nv_bfloat16 g_xh[MTOT*HID];
__device__ __nv_bfloat16 g_xl[MTOT*HID];
__device__ __nv_bfloat16 g_wh[4][HID*HID];
__device__ __nv_bfloat16 g_wl[4][HID*HID];
__device__ __nv_bfloat16 g_qh[BB*NH*SS*DH];
__device__ __nv_bfloat16 g_ql[BB*NH*SS*DH];
__device__ __nv_bfloat16 g_kh[BB*NH*SS*DH];
__device__ __nv_bfloat16 g_kl[BB*NH*SS*DH];
__device__ __nv_bfloat16 g_vh[BB*NH*SS*DH];
__device__ __nv_bfloat16 g_vl[BB*NH*SS*DH];

/* ---------------- helpers ---------------- */
__device__ __forceinline__ uint32_t smem_u32(const void* p) {
    uint32_t a;
    asm("{ .reg .u64 t; cvta.to.shared.u64 t, %1; cvt.u32.u64 %0, t; }" : "=r"(a) : "l"(p));
    return a;
}
#define CP_ASYNC16(dst, src) asm volatile("cp.async.cg.shared.global [%0], [%1], 16;" :: "r"(dst), "l"(src))
#define CP_COMMIT()          asm volatile("cp.async.commit_group;" ::: "memory")
#define CP_WAIT1()           asm volatile("cp.async.wait_group 1;" ::: "memory")
#define CP_WAIT0()           asm volatile("cp.async.wait_group 0;" ::: "memory")

#define LDMX4(r0,r1,r2,r3,addr) \
    asm volatile("ldmatrix.sync.aligned.m8n8.x4.shared.b16 {%0,%1,%2,%3}, [%4];" \
        : "=r"(r0), "=r"(r1), "=r"(r2), "=r"(r3) : "r"(addr))
#define LDMX4T(r0,r1,r2,r3,addr) \
    asm volatile("ldmatrix.sync.aligned.m8n8.x4.trans.shared.b16 {%0,%1,%2,%3}, [%4];" \
        : "=r"(r0), "=r"(r1), "=r"(r2), "=r"(r3) : "r"(addr))

#define MMA16816(c, a, b) \
    asm volatile("mma.sync.aligned.m16n8k16.row.col.f32.bf16.bf16.f32 " \
        "{%0,%1,%2,%3}, {%4,%5,%6,%7}, {%8,%9}, {%0,%1,%2,%3};" \
        : "+f"((c)[0]), "+f"((c)[1]), "+f"((c)[2]), "+f"((c)[3]) \
        : "r"((a)[0]), "r"((a)[1]), "r"((a)[2]), "r"((a)[3]), "r"((b)[0]), "r"((b)[1]))

__device__ __forceinline__ void split2(float x, float y, __nv_bfloat162& hi, __nv_bfloat162& lo) {
    __nv_bfloat16 h0 = __float2bfloat16(x), h1 = __float2bfloat16(y);
    lo = __nv_bfloat162(__float2bfloat16(x - __bfloat162float(h0)),
                        __float2bfloat16(y - __bfloat162float(h1)));
    hi = __nv_bfloat162(h0, h1);
}

/* ---------------- fused fp32 -> bf16 hi/lo split ---------------- */
__global__ void split_multi(const float4* __restrict__ X,
                            const float4* __restrict__ W0, const float4* __restrict__ W1,
                            const float4* __restrict__ W2, const float4* __restrict__ W3,
                            __nv_bfloat162* __restrict__ xh, __nv_bfloat162* __restrict__ xl,
                            __nv_bfloat162* __restrict__ wh, __nv_bfloat162* __restrict__ wl)
{
    int r = blockIdx.y;
    const float4* src;
    __nv_bfloat162 *hi, *lo;
    int n4;
    if (r == 0) { src = X; hi = xh; lo = xl; n4 = MTOT * HID / 4; }
    else {
        src = (r == 1) ? W0 : (r == 2) ? W1 : (r == 3) ? W2 : W3;
        hi = wh + (size_t)(r - 1) * (HID * HID / 2);
        lo = wl + (size_t)(r - 1) * (HID * HID / 2);
        n4 = HID * HID / 4;
    }
    for (int i = blockIdx.x * blockDim.x + threadIdx.x; i < n4; i += gridDim.x * blockDim.x) {
        float4 x = src[i];
        __nv_bfloat162 h0, l0, h1, l1;
        split2(x.x, x.y, h0, l0);
        split2(x.z, x.w, h1, l1);
        hi[2*i] = h0; hi[2*i+1] = h1;
        lo[2*i] = l0; lo[2*i+1] = l1;
    }
}

/* ---------------- mma.sync split GEMM, SW128-swizzled smem, 3-stage ----------------
 * MODE 0 additionally streams zeros over the attn-output region (zptr), 6 float4
 * stores per thread per K-iter with evict-first hint, overlapped with compute. */
extern __shared__ char dyn_smem[];

#define GT_TILE  8192
#define GT_STAGE 32768

__device__ __forceinline__ uint32_t sw_phys(uint32_t r, uint32_t colb) {
    uint32_t rowlin = ((r >> 1) << 7) + ((r & 1) << 6);
    return (rowlin + colb) ^ ((rowlin >> 3) & 0x70);
}

template<int MODE>
__global__ __launch_bounds__(256, 2)
void mma_gemm(const __nv_bfloat16* __restrict__ Ah, const __nv_bfloat16* __restrict__ Al,
              const __nv_bfloat16* __restrict__ Bh, const __nv_bfloat16* __restrict__ Bl,
              float* __restrict__ Y,
              __nv_bfloat16* __restrict__ qh, __nv_bfloat16* __restrict__ ql,
              __nv_bfloat16* __restrict__ kh, __nv_bfloat16* __restrict__ kl,
              __nv_bfloat16* __restrict__ vh, __nv_bfloat16* __restrict__ vl,
              float* __restrict__ zptr)
{
    uint32_t sb = smem_u32(dyn_smem);
    int tid = threadIdx.x, warp = tid >> 5, lane = tid & 31;
    int warpM = warp >> 2, warpN = warp & 3;
    int bm = blockIdx.y * 128, bn = blockIdx.x * 128;
    int cta = blockIdx.y * gridDim.x + blockIdx.x;

    float acc[4][4][4];
#pragma unroll
    for (int i = 0; i < 4; i++)
#pragma unroll
        for (int j = 0; j < 4; j++)
#pragma unroll
            for (int t = 0; t < 4; t++) acc[i][j][t] = 0.f;

    const __nv_bfloat16* srcs[4] = {Ah, Al, Bh, Bl};

    auto issue_stage = [&](int s, int k0) {
        uint32_t base = sb + s * GT_STAGE;
#pragma unroll
        for (int v = 0; v < 8; v++) {
            int idx = tid + v * 256;
            int t = idx >> 9;
            uint32_t r = (idx >> 2) & 127, seg = idx & 3;
            int rbase = (t < 2) ? bm : bn;
            const __nv_bfloat16* src = srcs[t] + (size_t)(rbase + r) * 1024 + k0 + seg * 8;
            uint32_t dst = base + t * GT_TILE + sw_phys(r, seg * 16);
            CP_ASYNC16(dst, src);
        }
        CP_COMMIT();
    };

    uint32_t aOff[4][2], bOff[2][2];
#pragma unroll
    for (int mt = 0; mt < 4; mt++) {
        uint32_t R = warpM * 64 + mt * 16 + (lane & 7) + ((lane >> 3) & 1) * 8;
#pragma unroll
        for (int ks = 0; ks < 2; ks++)
            aOff[mt][ks] = sw_phys(R, (lane >> 4) * 16 + ks * 32);
    }
#pragma unroll
    for (int j = 0; j < 2; j++) {
        uint32_t R = warpN * 32 + j * 16 + (lane & 7) + ((lane >> 4) & 1) * 8;
#pragma unroll
        for (int ks = 0; ks < 2; ks++)
            bOff[j][ks] = sw_phys(R, ((lane >> 3) & 1) * 16 + ks * 32);
    }

    issue_stage(0, 0);
    issue_stage(1, 32);

    int stg = 0;
    for (int it = 0; it < 32; it++) {
        if (it == 31) CP_WAIT0(); else CP_WAIT1();
        __syncthreads();
        if (it + 2 < 32) {
            int s2 = stg + 2; if (s2 >= 3) s2 -= 3;
            issue_stage(s2, (it + 2) * 32);
        }
        /* overlapped zero-fill of the attn tensor (MODE 0 only) */
        if (MODE == 0 && zptr) {
#pragma unroll
            for (int v = 0; v < 6; v++) {
                size_t g4 = ((size_t)(it * 6 + v) * 768 + cta) * 256 + tid;
                if (g4 < ATTN_F4) {
                    float4* p = (float4*)zptr + g4;
                    asm volatile("st.global.cs.v4.f32 [%0], {%1,%1,%1,%1};"
                                 :: "l"(p), "f"(0.f) : "memory");
                }
            }
        }
        uint32_t st = sb + stg * GT_STAGE;

#pragma unroll
        for (int ks = 0; ks < 2; ks++) {
            uint32_t aH[4][4], aL[4][4], bb[4][2];
#pragma unroll
            for (int mt = 0; mt < 4; mt++)
                LDMX4(aH[mt][0], aH[mt][1], aH[mt][2], aH[mt][3], st + aOff[mt][ks]);
            LDMX4(bb[0][0], bb[0][1], bb[1][0], bb[1][1], st + 2 * GT_TILE + bOff[0][ks]);
            LDMX4(bb[2][0], bb[2][1], bb[3][0], bb[3][1], st + 2 * GT_TILE + bOff[1][ks]);
#pragma unroll
            for (int mt = 0; mt < 4; mt++)
#pragma unroll
                for (int nt = 0; nt < 4; nt++)
                    MMA16816(acc[mt][nt], aH[mt], bb[nt]);
#pragma unroll
            for (int mt = 0; mt < 4; mt++)
                LDMX4(aL[mt][0], aL[mt][1], aL[mt][2], aL[mt][3], st + GT_TILE + aOff[mt][ks]);
#pragma unroll
            for (int mt = 0; mt < 4; mt++)
#pragma unroll
                for (int nt = 0; nt < 4; nt++)
                    MMA16816(acc[mt][nt], aL[mt], bb[nt]);
            LDMX4(bb[0][0], bb[0][1], bb[1][0], bb[1][1], st + 3 * GT_TILE + bOff[0][ks]);
            LDMX4(bb[2][0], bb[2][1], bb[3][0], bb[3][1], st + 3 * GT_TILE + bOff[1][ks]);
#pragma unroll
            for (int mt = 0; mt < 4; mt++)
#pragma unroll
                for (int nt = 0; nt < 4; nt++)
                    MMA16816(acc[mt][nt], aH[mt], bb[nt]);
        }
        if (++stg == 3) stg = 0;
    }

    int row0 = lane >> 2, col0 = (lane & 3) * 2;
    __nv_bfloat16 *Yh = nullptr, *Yl = nullptr;
    int nbase = 0;
    if (MODE == 0) {
        int mat = blockIdx.x >> 3;
        Yh = (mat == 0) ? qh : ((mat == 1) ? kh : vh);
        Yl = (mat == 0) ? ql : ((mat == 1) ? kl : vl);
        nbase = (blockIdx.x & 7) * 128;
    }
#pragma unroll
    for (int mt = 0; mt < 4; mt++) {
#pragma unroll
        for (int half = 0; half < 2; half++) {
            int m = bm + warpM * 64 + mt * 16 + row0 + half * 8;
            int b = m >> 11, s = m & 2047;
#pragma unroll
            for (int nt = 0; nt < 4; nt++) {
                float x0 = acc[mt][nt][half * 2 + 0];
                float x1 = acc[mt][nt][half * 2 + 1];
                if (MODE == 0) {
                    int n = nbase + warpN * 32 + nt * 8 + col0;
                    int h = n >> 6, d0 = n & 63;
                    size_t idx = (((size_t)b * NH + h) * SS + s) * DH + d0;
                    __nv_bfloat162 hi, lo;
                    split2(x0, x1, hi, lo);
                    *(__nv_bfloat162*)(Yh + idx) = hi;
                    *(__nv_bfloat162*)(Yl + idx) = lo;
                } else {
                    int n = bn + warpN * 32 + nt * 8 + col0;
                    float2 v2; v2.x = x0; v2.y = x1;
                    *(float2*)(Y + (size_t)m * HID + n) = v2;
                }
            }
        }
    }
}

/* ---------------- tensor-core sliding-window attention ----------------
 * smem: Sh @0, Sl @35328, Qh @70656, Ql @75264, KV x3 @79872, inv[32] @107520.
 */
#define WW 544
#define SSTR 552
#define OSH 0u
#define OSL 35328u
#define OQH 70656u
#define OQL 75264u
#define OKV 79872u
#define OINV 107520u
#define ATTN_SMEM 107648

__global__ __launch_bounds__(256, 2)
void attn_kernel(float* __restrict__ attn_out, int write_attn)
{
    char* sm = dyn_smem;
    uint32_t sb = smem_u32(sm);
    int tid = threadIdx.x, warp = tid >> 5, lane = tid & 31;
    int bh = blockIdx.y;
    int i0 = blockIdx.x * 32;
    int b = bh >> 4, h = bh & 15;
    size_t base = (size_t)bh * SS * DH;
    const __nv_bfloat16 *Qh = g_qh + base, *Ql = g_ql + base;
    const __nv_bfloat16 *Kh = g_kh + base, *Kl = g_kl + base;
    const __nv_bfloat16 *Vh = g_vh + base, *Vl = g_vl + base;
    int jlo = i0 - HALF;

    /* load Q hi/lo tile: 32x64 */
    {
        int row = tid >> 3, seg = tid & 7;
        uint4 vh4 = *(const uint4*)(Qh + (size_t)(i0 + row) * DH + seg * 8);
        uint4 vl4 = *(const uint4*)(Ql + (size_t)(i0 + row) * DH + seg * 8);
        *(uint4*)(sm + OQH + row * 144 + seg * 16) = vh4;
        *(uint4*)(sm + OQL + row * 144 + seg * 16) = vl4;
    }

    auto load_chunk = [&](const __nv_bfloat16* Mh, const __nv_bfloat16* Ml, int c, int buf) {
#pragma unroll
        for (int u = 0; u < 2; u++) {
            int idx = tid + u * 256;
            int hl = idx >> 8, r = (idx >> 3) & 31, seg = idx & 7;
            int j = jlo + c * 32 + r;
            j = (j < 0) ? 0 : ((j > SS - 1) ? SS - 1 : j);
            const __nv_bfloat16* src = (hl ? Ml : Mh) + (size_t)j * DH + seg * 8;
            uint32_t dst = sb + OKV + buf * 9216 + hl * 4608 + r * 144 + seg * 16;
            CP_ASYNC16(dst, src);
        }
        CP_COMMIT();
    };

    /* ---------- phase 1: scores ---------- */
    {
        int mt = warp >> 2, nt = warp & 3;
        uint32_t aoffQ = (uint32_t)((mt * 16 + (lane & 15)) * 144 + (lane >> 4) * 16);
        uint32_t boffK4 = (uint32_t)((nt * 8 + (lane & 7)) * 144 + ((lane >> 3) & 3) * 16);

        load_chunk(Kh, Kl, 0, 0);
        load_chunk(Kh, Kl, 1, 1);
        __syncthreads();

        uint32_t qHf[4][4], qLf[4][4];
#pragma unroll
        for (int ks = 0; ks < 4; ks++) {
            LDMX4(qHf[ks][0], qHf[ks][1], qHf[ks][2], qHf[ks][3], sb + OQH + aoffQ + ks * 32);
            LDMX4(qLf[ks][0], qLf[ks][1], qLf[ks][2], qLf[ks][3], sb + OQL + aoffQ + ks * 32);
        }

        for (int c = 0; c < 17; c++) {
            if (c == 16) CP_WAIT0(); else CP_WAIT1();
            __syncthreads();
            if (c + 2 < 17) load_chunk(Kh, Kl, c + 2, (c + 2) % 3);
            uint32_t kb = sb + OKV + (c % 3) * 9216;
            float acc[4] = {0.f, 0.f, 0.f, 0.f};
            uint32_t bHf[4][2], bLf[4][2];
            LDMX4(bHf[0][0], bHf[0][1], bHf[1][0], bHf[1][1], kb + boffK4);
            LDMX4(bHf[2][0], bHf[2][1], bHf[3][0], bHf[3][1], kb + boffK4 + 64);
            LDMX4(bLf[0][0], bLf[0][1], bLf[1][0], bLf[1][1], kb + 4608 + boffK4);
            LDMX4(bLf[2][0], bLf[2][1], bLf[3][0], bLf[3][1], kb + 4608 + boffK4 + 64);
#pragma unroll
            for (int ks = 0; ks < 4; ks++) {
                MMA16816(acc, qHf[ks], bHf[ks]);
                MMA16816(acc, qLf[ks], bHf[ks]);
                MMA16816(acc, qHf[ks], bLf[ks]);
            }
            int colb = c * 32 + nt * 8 + (lane & 3) * 2;
#pragma unroll
            for (int half = 0; half < 2; half++) {
                int r = mt * 16 + (lane >> 2) + half * 8;
                int i = i0 + r;
                int j0 = jlo + colb, j1 = j0 + 1;
                float s0 = acc[half * 2 + 0] * SCALE;
                float s1 = acc[half * 2 + 1] * SCALE;
                if (!((j0 >= 0) && (j0 < SS) && (j0 >= i - HALF) && (j0 <= i + HALF))) s0 = -1e30f;
                if (!((j1 >= 0) && (j1 < SS) && (j1 >= i - HALF) && (j1 <= i + HALF))) s1 = -1e30f;
                __nv_bfloat162 hi, lo;
                split2(s0, s1, hi, lo);
                *(__nv_bfloat162*)(sm + OSH + (r * SSTR + colb) * 2) = hi;
                *(__nv_bfloat162*)(sm + OSL + (r * SSTR + colb) * 2) = lo;
            }
        }
        __syncthreads();
    }

    /* prefetch first two V chunks so softmax hides the load latency */
    load_chunk(Vh, Vl, 0, 0);
    load_chunk(Vh, Vl, 1, 1);

    /* ---------- phase 2: softmax, 2-pass, deferred normalization ---------- */
    {
        for (int rr = 0; rr < 4; rr++) {
            int r = warp * 4 + rr;
            uint32_t rh = OSH + r * SSTR * 2, rl = OSL + r * SSTR * 2;
            float mx = -1e30f;
            for (int pc = lane; pc < 272; pc += 32) {
                __nv_bfloat162 hh = *(__nv_bfloat162*)(sm + rh + pc * 4);
                __nv_bfloat162 ll = *(__nv_bfloat162*)(sm + rl + pc * 4);
                float s0 = __bfloat162float(hh.x) + __bfloat162float(ll.x);
                float s1 = __bfloat162float(hh.y) + __bfloat162float(ll.y);
                mx = fmaxf(mx, fmaxf(s0, s1));
            }
#pragma unroll
            for (int o = 16; o > 0; o >>= 1) mx = fmaxf(mx, __shfl_xor_sync(0xffffffffu, mx, o));
            float sum = 0.f;
            for (int pc = lane; pc < 272; pc += 32) {
                __nv_bfloat162 hh = *(__nv_bfloat162*)(sm + rh + pc * 4);
                __nv_bfloat162 ll = *(__nv_bfloat162*)(sm + rl + pc * 4);
                float s0 = __bfloat162float(hh.x) + __bfloat162float(ll.x);
                float s1 = __bfloat162float(hh.y) + __bfloat162float(ll.y);
                float e0 = __expf(s0 - mx);
                float e1 = __expf(s1 - mx);
                sum += e0 + e1;
                __nv_bfloat162 hi, lo;
                split2(e0, e1, hi, lo);
                *(__nv_bfloat162*)(sm + rh + pc * 4) = hi;
                *(__nv_bfloat162*)(sm + rl + pc * 4) = lo;
            }
#pragma unroll
            for (int o = 16; o > 0; o >>= 1) sum += __shfl_xor_sync(0xffffffffu, sum, o);
            if (lane == 0) ((float*)(sm + OINV))[r] = 1.f / sum;
            /* zero-pad S cols 544..551 (read by boundary float4s in write phase) */
            if (lane < 4) {
                *(uint32_t*)(sm + rh + (272 + lane) * 4) = 0;
                *(uint32_t*)(sm + rl + (272 + lane) * 4) = 0;
            }
        }
        __syncthreads();
    }

    /* ---------- phase 2.5: write attn band only (zeros pre-filled by GEMM) ---------- */
    if (write_attn) {
        for (int rr = 0; rr < 4; rr++) {
            int r = warp * 4 + rr;
            int i = i0 + r;
            float inv = ((float*)(sm + OINV))[r];
            float* row = attn_out + ((size_t)bh * SS + i) * SS;
            uint32_t rh = OSH + r * SSTR * 2, rl = OSL + r * SSTR * 2;
            int jstart = i - HALF; if (jstart < 0) jstart = 0; jstart &= ~3;
            int jend = i + HALF + 1; if (jend > SS) jend = SS;
            for (int j4 = jstart + lane * 4; j4 < jend; j4 += 128) {
                int cidx = j4 - jlo;   /* multiple of 4, in [0, 544) */
                uint2 uh = *(uint2*)(sm + rh + cidx * 2);
                uint2 ul = *(uint2*)(sm + rl + cidx * 2);
                __nv_bfloat162 h0 = *(__nv_bfloat162*)&uh.x;
                __nv_bfloat162 h1 = *(__nv_bfloat162*)&uh.y;
                __nv_bfloat162 l0 = *(__nv_bfloat162*)&ul.x;
                __nv_bfloat162 l1 = *(__nv_bfloat162*)&ul.y;
                float4 v4;
                v4.x = (__bfloat162float(h0.x) + __bfloat162float(l0.x)) * inv;
                v4.y = (__bfloat162float(h0.y) + __bfloat162float(l0.y)) * inv;
                v4.z = (__bfloat162float(h1.x) + __bfloat162float(l1.x)) * inv;
                v4.w = (__bfloat162float(h1.y) + __bfloat162float(l1.y)) * inv;
                *(float4*)(row + j4) = v4;
            }
        }
    }

    /* ---------- phase 3: PV (on unnormalized E; scale at epilogue) ---------- */
    {
        int mtp = warp >> 2;
        int ntb = (warp & 3) * 2;
        float oacc[2][4];
#pragma unroll
        for (int p = 0; p < 2; p++)
#pragma unroll
            for (int t = 0; t < 4; t++) oacc[p][t] = 0.f;

        uint32_t aoffP = (uint32_t)((mtp * 16 + (lane & 15)) * SSTR * 2 + (lane >> 4) * 16);
        uint32_t vrow4 = (uint32_t)((((lane & 7) + ((lane >> 3) & 1) * 8)) * 144 + (lane >> 4) * 16);

        for (int c = 0; c < 17; c++) {
            if (c == 16) CP_WAIT0(); else CP_WAIT1();
            __syncthreads();
            if (c + 2 < 17) load_chunk(Vh, Vl, c + 2, (c + 2) % 3);
            uint32_t vb = sb + OKV + (c % 3) * 9216;
#pragma unroll
            for (int ks = 0; ks < 2; ks++) {
                uint32_t aH[4], aL[4];
                LDMX4(aH[0], aH[1], aH[2], aH[3], sb + OSH + aoffP + (c * 32 + ks * 16) * 2);
                LDMX4(aL[0], aL[1], aL[2], aL[3], sb + OSL + aoffP + (c * 32 + ks * 16) * 2);
                uint32_t bHf[2][2], bLf[2][2];
                uint32_t va = vb + vrow4 + ks * 16 * 144 + ntb * 16;
                LDMX4T(bHf[0][0], bHf[0][1], bHf[1][0], bHf[1][1], va);
                LDMX4T(bLf[0][0], bLf[0][1], bLf[1][0], bLf[1][1], va + 4608);
#pragma unroll
                for (int p = 0; p < 2; p++) {
                    MMA16816(oacc[p], aH, bHf[p]);
                    MMA16816(oacc[p], aL, bHf[p]);
                    MMA16816(oacc[p], aH, bLf[p]);
                }
            }
        }

        int row0 = lane >> 2, col0 = (lane & 3) * 2;
        float invA = ((float*)(sm + OINV))[mtp * 16 + row0];
        float invB = ((float*)(sm + OINV))[mtp * 16 + row0 + 8];
#pragma unroll
        for (int p = 0; p < 2; p++) {
            int nt = ntb + p;
#pragma unroll
            for (int half = 0; half < 2; half++) {
                float inv = half ? invB : invA;
                int i = i0 + mtp * 16 + row0 + half * 8;
                size_t m = (size_t)b * SS + i;
                int d = nt * 8 + col0;
                float x0 = oacc[p][half * 2 + 0] * inv;
                float x1 = oacc[p][half * 2 + 1] * inv;
                __nv_bfloat162 hi, lo;
                split2(x0, x1, hi, lo);
                size_t idx = m * HID + h * DH + d;
                *(__nv_bfloat162*)(g_xh + idx) = hi;
                *(__nv_bfloat162*)(g_xl + idx) = lo;
            }
        }
    }
}

/* ---------------- launch ---------------- */
extern "C" void kernel_launch(void* const* d_in, const int* in_sizes, int n_in,
                              void* d_out, int out_size)
{
    const float* X = (const float*)d_in[0];
    const float* W[4] = {(const float*)d_in[1], (const float*)d_in[2],
                         (const float*)d_in[3], (const float*)d_in[4]};
    float* out = (float*)d_out;

    __nv_bfloat16 *xh, *xl, *wh, *wl, *qh, *ql, *kh, *kl, *vh, *vl;
    cudaGetSymbolAddress((void**)&xh, g_xh);
    cudaGetSymbolAddress((void**)&xl, g_xl);
    cudaGetSymbolAddress((void**)&wh, g_wh);
    cudaGetSymbolAddress((void**)&wl, g_wl);
    cudaGetSymbolAddress((void**)&qh, g_qh);
    cudaGetSymbolAddress((void**)&ql, g_ql);
    cudaGetSymbolAddress((void**)&kh, g_kh);
    cudaGetSymbolAddress((void**)&kl, g_kl);
    cudaGetSymbolAddress((void**)&vh, g_vh);
    cudaGetSymbolAddress((void**)&vl, g_vl);

    static int attr_set = -1;
    size_t gemm_smem = 3 * GT_STAGE;
    if (attr_set < 0) {
        cudaFuncSetAttribute(attn_kernel, cudaFuncAttributeMaxDynamicSharedMemorySize, ATTN_SMEM);
        cudaFuncSetAttribute(mma_gemm<0>, cudaFuncAttributeMaxDynamicSharedMemorySize, (int)gemm_smem);
        cudaFuncSetAttribute(mma_gemm<1>, cudaFuncAttributeMaxDynamicSharedMemorySize, (int)gemm_smem);
        attr_set = 1;
    }

    int write_attn = ((size_t)out_size >= (size_t)OUT_ELEMS + ATTN_ELEMS) ? 1 : 0;
    float* attn_out = write_attn ? (out + OUT_ELEMS) : out;

    split_multi<<<dim3(512, 5), 256>>>((const float4*)X,
                                       (const float4*)W[0], (const float4*)W[1],
                                       (const float4*)W[2], (const float4*)W[3],
                                       (__nv_bfloat162*)xh, (__nv_bfloat162*)xl,
                                       (__nv_bfloat162*)wh, (__nv_bfloat162*)wl);

    /* fused QKV GEMM (N=3072) + overlapped zero-fill of the attn tensor */
    mma_gemm<0><<<dim3(24, 32), 256, gemm_smem>>>(xh, xl, wh, wl, nullptr,
                                                  qh, ql, kh, kl, vh, vl,
                                                  write_attn ? attn_out : nullptr);

    dim3 agrid(SS / 32, BB * NH);
    attn_kernel<<<agrid, 256, ATTN_SMEM>>>(attn_out, write_attn);

    mma_gemm<1><<<dim3(8, 32), 256, gemm_smem>>>(xh, xl,
                                                 wh + (size_t)3 * HID * HID,
                                                 wl + (size_t)3 * HID * HID,
                                                 out, nullptr, nullptr, nullptr, nullptr, nullptr, nullptr,
                                                 nullptr);
}